// round 6
// baseline (speedup 1.0000x reference)
#include <cuda_runtime.h>
#include <cuda_fp16.h>
#include <math.h>

#define NNODES 80000
#define DIM    128
#define DEMB   64
#define NT     128
#define NG     8000
#define NUMP   40000
#define NEMAX  2560000

typedef unsigned long long ull;

__device__ __forceinline__ ull ffma2(ull a, ull b, ull c) {
    ull d;
    asm("fma.rn.f32x2 %0, %1, %2, %3;" : "=l"(d) : "l"(a), "l"(b), "l"(c));
    return d;
}
__device__ __forceinline__ ull bcast2(float a) {
    ull d;
    asm("mov.b64 %0, {%1, %1};" : "=l"(d) : "f"(a));
    return d;
}
__device__ __forceinline__ float2 unpack2(ull v) {
    float2 f;
    asm("mov.b64 {%0, %1}, %2;" : "=f"(f.x), "=f"(f.y) : "l"(v));
    return f;
}

// ---------------- scratch (static device arrays; no allocation) ----------------
__device__ int g_rowptr[NNODES + 1];
__device__ int g_cursor[NNODES];
__device__ int g_flag[NNODES];
__device__ int g_list[NT + NG];
__device__ int g_nlist;
__device__ int g_bsum[128];
__device__ int g_esrc[NEMAX];                                 // CSR: src per edge, grouped by dst
__device__ __align__(16) __half g_xh[(size_t)NNODES * DIM];   // fp16 copy of x
__device__ __align__(16) float g_p [(size_t)NNODES * DEMB];   // relu(agg1@W1+b1)@W2
__device__ __align__(16) float g_pa[(size_t)NNODES * DEMB];   // agg2 output (listed rows only)
__device__ __align__(16) float g_At[DIM * NT];                // A transposed [k][t]
__device__ __align__(16) float g_Bt[(size_t)DIM * NG];        // B transposed [k][g]

// ---------------- zero counters/flags ----------------
__global__ void zero_kernel() {
    int i = blockIdx.x * blockDim.x + threadIdx.x;
    if (i <= NNODES) g_rowptr[i] = 0;
    if (i <  NNODES) g_flag[i] = 0;
    if (i == 0) g_nlist = 0;
}

// ---------------- combo: hist(int4) + x->fp16 + flag/list ----------------
__global__ void combo_kernel(const float* __restrict__ x,
                             const int* __restrict__ dst, int ne, int hb,
                             const int* __restrict__ tf, const int* __restrict__ gene) {
    int b = blockIdx.x;
    if (b < hb) {                       // histogram, 4 edges/thread
        int i = b * 256 + threadIdx.x;
        int ne4 = ne >> 2;
        if (i < ne4) {
            int4 d4 = reinterpret_cast<const int4*>(dst)[i];
            atomicAdd(&g_rowptr[d4.x + 1], 1);
            atomicAdd(&g_rowptr[d4.y + 1], 1);
            atomicAdd(&g_rowptr[d4.z + 1], 1);
            atomicAdd(&g_rowptr[d4.w + 1], 1);
        }
        if (b == 0 && threadIdx.x == 0) {
            for (int e = ne4 * 4; e < ne; e++) atomicAdd(&g_rowptr[dst[e] + 1], 1);
        }
    } else if (b < hb + 5000) {         // x -> fp16 (one thread per 8 floats)
        int i = (b - hb) * 256 + threadIdx.x;
        if (i < NNODES * DIM / 8) {
            float4 a = reinterpret_cast<const float4*>(x)[2 * i];
            float4 bq = reinterpret_cast<const float4*>(x)[2 * i + 1];
            __half2 h0 = __floats2half2_rn(a.x, a.y);
            __half2 h1 = __floats2half2_rn(a.z, a.w);
            __half2 h2 = __floats2half2_rn(bq.x, bq.y);
            __half2 h3 = __floats2half2_rn(bq.z, bq.w);
            uint4 o;
            o.x = *reinterpret_cast<unsigned*>(&h0);
            o.y = *reinterpret_cast<unsigned*>(&h1);
            o.z = *reinterpret_cast<unsigned*>(&h2);
            o.w = *reinterpret_cast<unsigned*>(&h3);
            reinterpret_cast<uint4*>(g_xh)[i] = o;
        }
    } else {                            // flag + compact list
        int i = (b - hb - 5000) * 256 + threadIdx.x;
        if (i < NT) {
            int nd = NUMP + tf[i];
            if (atomicExch(&g_flag[nd], 1) == 0) g_list[atomicAdd(&g_nlist, 1)] = nd;
        }
        if (i < NG) {
            int nd = NUMP + gene[i];
            if (atomicExch(&g_flag[nd], 1) == 0) g_list[atomicAdd(&g_nlist, 1)] = nd;
        }
    }
}

// ---------------- scan over g_rowptr ----------------
__global__ __launch_bounds__(1024) void scan1_kernel() {
    __shared__ int wsum[32];
    int gid = blockIdx.x * 1024 + threadIdx.x;
    int lane = threadIdx.x & 31, wid = threadIdx.x >> 5;
    int s = (gid <= NNODES) ? g_rowptr[gid] : 0;
#pragma unroll
    for (int o = 1; o < 32; o <<= 1) { int t = __shfl_up_sync(0xffffffffu, s, o); if (lane >= o) s += t; }
    if (lane == 31) wsum[wid] = s;
    __syncthreads();
    if (wid == 0) {
        int w = wsum[lane];
#pragma unroll
        for (int o = 1; o < 32; o <<= 1) { int t = __shfl_up_sync(0xffffffffu, w, o); if (lane >= o) w += t; }
        wsum[lane] = w;
    }
    __syncthreads();
    if (wid > 0) s += wsum[wid - 1];
    if (gid <= NNODES) g_rowptr[gid] = s;
    if (threadIdx.x == 1023) g_bsum[blockIdx.x] = s;
}

__global__ void scan2_kernel(int nb) {
    int lane = threadIdx.x;
    int carry = 0;
    for (int base = 0; base < nb; base += 32) {
        int v = (base + lane < nb) ? g_bsum[base + lane] : 0;
#pragma unroll
        for (int o = 1; o < 32; o <<= 1) { int t = __shfl_up_sync(0xffffffffu, v, o); if (lane >= o) v += t; }
        v += carry;
        if (base + lane < nb) g_bsum[base + lane] = v;
        carry = __shfl_sync(0xffffffffu, v, 31);
    }
}

__global__ __launch_bounds__(1024) void scan3_kernel() {
    int gid = blockIdx.x * 1024 + threadIdx.x;
    if (gid > NNODES) return;
    int v = g_rowptr[gid];
    if (blockIdx.x > 0) v += g_bsum[blockIdx.x - 1];
    g_rowptr[gid] = v;
    if (gid < NNODES) g_cursor[gid] = v;
}

// ---------------- scatter, 4 edges per thread ----------------
__global__ void scatter_kernel(const int* __restrict__ src, const int* __restrict__ dst, int ne) {
    int i = blockIdx.x * blockDim.x + threadIdx.x;
    int ne4 = ne >> 2;
    if (i < ne4) {
        int4 s4 = reinterpret_cast<const int4*>(src)[i];
        int4 d4 = reinterpret_cast<const int4*>(dst)[i];
        g_esrc[atomicAdd(&g_cursor[d4.x], 1)] = s4.x;
        g_esrc[atomicAdd(&g_cursor[d4.y], 1)] = s4.y;
        g_esrc[atomicAdd(&g_cursor[d4.z], 1)] = s4.z;
        g_esrc[atomicAdd(&g_cursor[d4.w], 1)] = s4.w;
    }
    if (i == 0) {
        for (int e = ne4 * 4; e < ne; e++)
            g_esrc[atomicAdd(&g_cursor[dst[e]], 1)] = src[e];
    }
}

// ---------------- FUSED: agg1 (CSR gather into smem) + p = relu(agg@W1+b1)@W2 ----------------
// 512 threads, 64 dsts per block. Agg: warp w handles rows w*4..w*4+3,
// half-warps gather 2 edges at a time (8-edge unrolled main loop).
__global__ __launch_bounds__(512) void agg_gemm_kernel(
    const float* __restrict__ W1, const float* __restrict__ b1,
    const float* __restrict__ W2) {
    extern __shared__ float sm[];
    float* W1s = sm;                       // 128*128
    float* W2s = W1s + 128 * 128;          // 128*64
    float* Is  = W2s + 128 * 64;           // 64*128 (aggregated means)
    float* Hs  = Is  + 64 * 128;           // 64*128
    float* b1s = Hs  + 64 * 128;           // 128
    int tid = threadIdx.x;

    for (int i = tid; i < 128 * 128 / 4; i += 512)
        reinterpret_cast<float4*>(W1s)[i] = reinterpret_cast<const float4*>(W1)[i];
    for (int i = tid; i < 128 * 64 / 4; i += 512)
        reinterpret_cast<float4*>(W2s)[i] = reinterpret_cast<const float4*>(W2)[i];
    if (tid < 128) b1s[tid] = b1[tid];

    int row0 = blockIdx.x * 64;  // 1250 blocks * 64 = 80000 exact
    int warp = tid >> 5, lane = tid & 31;
    int half = lane >> 4, sub = lane & 15;

    // ---- aggregation phase: 4 dsts per warp ----
#pragma unroll
    for (int rr = 0; rr < 4; rr++) {
        int r = warp * 4 + rr;
        int d = row0 + r;
        int beg = g_rowptr[d], end = g_rowptr[d + 1];
        float acc[8];
#pragma unroll
        for (int k = 0; k < 8; k++) acc[k] = 0.f;

        int j = beg;
        for (; j + 7 < end; j += 8) {
            int s0 = g_esrc[j + half];
            int s1 = g_esrc[j + 2 + half];
            int s2 = g_esrc[j + 4 + half];
            int s3 = g_esrc[j + 6 + half];
            uint4 va = *reinterpret_cast<const uint4*>(g_xh + (size_t)s0 * DIM + sub * 8);
            uint4 vb = *reinterpret_cast<const uint4*>(g_xh + (size_t)s1 * DIM + sub * 8);
            uint4 vc = *reinterpret_cast<const uint4*>(g_xh + (size_t)s2 * DIM + sub * 8);
            uint4 vd = *reinterpret_cast<const uint4*>(g_xh + (size_t)s3 * DIM + sub * 8);
            __half2 p0 = __hadd2(*reinterpret_cast<__half2*>(&va.x), *reinterpret_cast<__half2*>(&vb.x));
            __half2 p1 = __hadd2(*reinterpret_cast<__half2*>(&va.y), *reinterpret_cast<__half2*>(&vb.y));
            __half2 p2 = __hadd2(*reinterpret_cast<__half2*>(&va.z), *reinterpret_cast<__half2*>(&vb.z));
            __half2 p3 = __hadd2(*reinterpret_cast<__half2*>(&va.w), *reinterpret_cast<__half2*>(&vb.w));
            __half2 q0 = __hadd2(*reinterpret_cast<__half2*>(&vc.x), *reinterpret_cast<__half2*>(&vd.x));
            __half2 q1 = __hadd2(*reinterpret_cast<__half2*>(&vc.y), *reinterpret_cast<__half2*>(&vd.y));
            __half2 q2 = __hadd2(*reinterpret_cast<__half2*>(&vc.z), *reinterpret_cast<__half2*>(&vd.z));
            __half2 q3 = __hadd2(*reinterpret_cast<__half2*>(&vc.w), *reinterpret_cast<__half2*>(&vd.w));
            float2 f;
            f = __half22float2(p0); acc[0] += f.x; acc[1] += f.y;
            f = __half22float2(p1); acc[2] += f.x; acc[3] += f.y;
            f = __half22float2(p2); acc[4] += f.x; acc[5] += f.y;
            f = __half22float2(p3); acc[6] += f.x; acc[7] += f.y;
            f = __half22float2(q0); acc[0] += f.x; acc[1] += f.y;
            f = __half22float2(q1); acc[2] += f.x; acc[3] += f.y;
            f = __half22float2(q2); acc[4] += f.x; acc[5] += f.y;
            f = __half22float2(q3); acc[6] += f.x; acc[7] += f.y;
        }
        for (; j < end; j += 2) {
            int jj = j + half;
            if (jj < end) {
                int s = g_esrc[jj];
                uint4 v = *reinterpret_cast<const uint4*>(g_xh + (size_t)s * DIM + sub * 8);
                float2 f;
                f = __half22float2(*reinterpret_cast<__half2*>(&v.x)); acc[0] += f.x; acc[1] += f.y;
                f = __half22float2(*reinterpret_cast<__half2*>(&v.y)); acc[2] += f.x; acc[3] += f.y;
                f = __half22float2(*reinterpret_cast<__half2*>(&v.z)); acc[4] += f.x; acc[5] += f.y;
                f = __half22float2(*reinterpret_cast<__half2*>(&v.w)); acc[6] += f.x; acc[7] += f.y;
            }
        }
#pragma unroll
        for (int k = 0; k < 8; k++) acc[k] += __shfl_xor_sync(0xffffffffu, acc[k], 16);
        if (half == 0) {
            float inv = 1.f / fmaxf((float)(end - beg), 1.f);
            float4* outp = reinterpret_cast<float4*>(Is + r * DIM + sub * 8);
            outp[0] = make_float4(acc[0] * inv, acc[1] * inv, acc[2] * inv, acc[3] * inv);
            outp[1] = make_float4(acc[4] * inv, acc[5] * inv, acc[6] * inv, acc[7] * inv);
        }
    }
    __syncthreads();

    int tr = warp, tc = lane;   // tr 0..15, tc 0..31

    // phase 1: H = relu(Is @ W1 + b1); thread -> 4 rows x 4 cols (2 f32x2 pairs)
    {
        ull acc[4][2];
#pragma unroll
        for (int i = 0; i < 4; i++) { acc[i][0] = 0ull; acc[i][1] = 0ull; }

        for (int d0 = 0; d0 < DIM; d0 += 4) {
            float ar[4][4];
#pragma unroll
            for (int i = 0; i < 4; i++) {
                float4 t = reinterpret_cast<const float4*>(Is + (tr * 4 + i) * DIM)[d0 >> 2];
                ar[i][0] = t.x; ar[i][1] = t.y; ar[i][2] = t.z; ar[i][3] = t.w;
            }
#pragma unroll
            for (int dd = 0; dd < 4; dd++) {
                ulonglong2 wv = *reinterpret_cast<const ulonglong2*>(W1s + (d0 + dd) * 128 + tc * 4);
#pragma unroll
                for (int i = 0; i < 4; i++) {
                    ull ap = bcast2(ar[i][dd]);
                    acc[i][0] = ffma2(ap, wv.x, acc[i][0]);
                    acc[i][1] = ffma2(ap, wv.y, acc[i][1]);
                }
            }
        }
        float4 bv = reinterpret_cast<const float4*>(b1s)[tc];
#pragma unroll
        for (int i = 0; i < 4; i++) {
            float2 lo = unpack2(acc[i][0]);
            float2 hi = unpack2(acc[i][1]);
            float4 o;
            o.x = fmaxf(lo.x + bv.x, 0.f);
            o.y = fmaxf(lo.y + bv.y, 0.f);
            o.z = fmaxf(hi.x + bv.z, 0.f);
            o.w = fmaxf(hi.y + bv.w, 0.f);
            reinterpret_cast<float4*>(Hs + (tr * 4 + i) * DIM)[tc] = o;
        }
    }
    __syncthreads();

    // phase 2: P = Hs @ W2; thread -> 4 rows x 2 cols (1 f32x2 pair)
    {
        ull acc[4];
#pragma unroll
        for (int i = 0; i < 4; i++) acc[i] = 0ull;

        for (int d0 = 0; d0 < DIM; d0 += 4) {
            float ar[4][4];
#pragma unroll
            for (int i = 0; i < 4; i++) {
                float4 t = reinterpret_cast<const float4*>(Hs + (tr * 4 + i) * DIM)[d0 >> 2];
                ar[i][0] = t.x; ar[i][1] = t.y; ar[i][2] = t.z; ar[i][3] = t.w;
            }
#pragma unroll
            for (int dd = 0; dd < 4; dd++) {
                ull wp = *reinterpret_cast<const ull*>(W2s + (d0 + dd) * 64 + tc * 2);
#pragma unroll
                for (int i = 0; i < 4; i++)
                    acc[i] = ffma2(bcast2(ar[i][dd]), wp, acc[i]);
            }
        }
#pragma unroll
        for (int i = 0; i < 4; i++) {
            int row = row0 + tr * 4 + i;
            float2 o = unpack2(acc[i]);
            reinterpret_cast<float2*>(g_p + (size_t)row * DEMB)[tc] = o;
        }
    }
}

// ---------------- agg2: warp per listed dst, half-warps gather 2 edges (fp32 rows, 256B) --------
__global__ __launch_bounds__(256) void agg2_csr_kernel() {
    int idx = blockIdx.x * 8 + (threadIdx.x >> 5);
    if (idx >= g_nlist) return;
    int d = g_list[idx];
    int lane = threadIdx.x & 31;
    int half = lane >> 4;
    int sub  = lane & 15;       // 16B chunk within 256B row (4 floats)
    int beg = g_rowptr[d], end = g_rowptr[d + 1];
    float acc[4] = {0.f, 0.f, 0.f, 0.f};

    int j = beg;
    for (; j + 3 < end; j += 4) {
        int s0 = g_esrc[j + half];
        int s1 = g_esrc[j + 2 + half];
        float4 va = *reinterpret_cast<const float4*>(g_p + (size_t)s0 * DEMB + sub * 4);
        float4 vb = *reinterpret_cast<const float4*>(g_p + (size_t)s1 * DEMB + sub * 4);
        acc[0] += va.x + vb.x; acc[1] += va.y + vb.y;
        acc[2] += va.z + vb.z; acc[3] += va.w + vb.w;
    }
    for (; j < end; j += 2) {
        int jj = j + half;
        if (jj < end) {
            int s = g_esrc[jj];
            float4 v = *reinterpret_cast<const float4*>(g_p + (size_t)s * DEMB + sub * 4);
            acc[0] += v.x; acc[1] += v.y; acc[2] += v.z; acc[3] += v.w;
        }
    }
#pragma unroll
    for (int k = 0; k < 4; k++) acc[k] += __shfl_xor_sync(0xffffffffu, acc[k], 16);
    if (half == 0) {
        float inv = 1.f / fmaxf((float)(end - beg), 1.f);
        reinterpret_cast<float4*>(g_pa + (size_t)d * DEMB + sub * 4)[0] =
            make_float4(acc[0] * inv, acc[1] * inv, acc[2] * inv, acc[3] * inv);
    }
}

// ---------------- half-MLP: OutT[k][r] = sum_d (pa[node_r][d] + b2[d]) * Whalf[d][k] (+bm1[k]) ------
__global__ __launch_bounds__(128) void half_mlp_kernel(
    const int* __restrict__ list, int nrows,
    const float* __restrict__ Whalf, const float* __restrict__ b2,
    const float* __restrict__ bm1, float* __restrict__ OutT, int ldo) {
    __shared__ __align__(8) float Wst[128 * 66];   // transposed [t][d], pad 66 (even) for ull loads
    __shared__ __align__(8) float es[DEMB];
    int tid = threadIdx.x;  // 128 (= t)

#pragma unroll 4
    for (int d = 0; d < DEMB; d++) Wst[tid * 66 + d] = Whalf[d * DIM + tid];
    float base = bm1 ? bm1[tid] : 0.f;

    for (int r = blockIdx.x; r < nrows; r += gridDim.x) {
        __syncthreads();
        if (tid < DEMB) {
            int node = NUMP + list[r];
            es[tid] = g_pa[(size_t)node * DEMB + tid] + b2[tid];
        }
        __syncthreads();
        ull acc = 0ull;
#pragma unroll 8
        for (int d = 0; d < DEMB; d += 2) {
            ull ep = *reinterpret_cast<const ull*>(es + d);
            ull wp = *reinterpret_cast<const ull*>(Wst + tid * 66 + d);
            acc = ffma2(ep, wp, acc);
        }
        float2 a2 = unpack2(acc);
        OutT[(size_t)tid * ldo + r] = base + a2.x + a2.y;
    }
}

// ---------------- pair kernel: out[t*NG+g] = softmax( relu(A[t]+B[g]) @ Wm2 + bm2 ) ----------------
__global__ __launch_bounds__(256) void pair_kernel(
    const float* __restrict__ Wm2, const float* __restrict__ bm2, float* __restrict__ out) {
    extern __shared__ float sm[];
    float* As = sm;                       // [k][t] 128*128
    float* Bs = sm + DIM * NT;            // [k][gl] 128*32
    float2* w2 = reinterpret_cast<float2*>(sm + DIM * NT + DIM * 32);
    int tid = threadIdx.x;  // 256

    for (int i = tid; i < DIM * NT / 4; i += 256)
        reinterpret_cast<float4*>(As)[i] = reinterpret_cast<const float4*>(g_At)[i];
    int g0 = blockIdx.x * 32;
    for (int i = tid; i < DIM * 32; i += 256) {
        int k = i >> 5, gl = i & 31;
        Bs[i] = g_Bt[(size_t)k * NG + g0 + gl];
    }
    if (tid < DIM) w2[tid] = reinterpret_cast<const float2*>(Wm2)[tid];
    __syncthreads();

    float bo0 = bm2[0], bo1 = bm2[1];
    int lane = tid & 31, warp = tid >> 5;
    ull accp[16];
#pragma unroll
    for (int i = 0; i < 16; i++) accp[i] = 0ull;

#pragma unroll 4
    for (int k = 0; k < DIM; k++) {
        float bv = Bs[k * 32 + lane];
        ull wp = *reinterpret_cast<const ull*>(&w2[k]);
#pragma unroll
        for (int i = 0; i < 16; i++) {
            float a = As[k * DIM + warp + 8 * i];
            float v = fmaxf(a + bv, 0.f);
            accp[i] = ffma2(bcast2(v), wp, accp[i]);
        }
    }

#pragma unroll
    for (int i = 0; i < 16; i++) {
        int t = warp + 8 * i;
        float2 a2 = unpack2(accp[i]);
        float o0 = a2.x + bo0, o1 = a2.y + bo1;
        float m  = fmaxf(o0, o1);
        float e0 = __expf(o0 - m), e1 = __expf(o1 - m);
        float inv = 1.f / (e0 + e1);
        reinterpret_cast<float2*>(out)[(size_t)t * NG + g0 + lane] = make_float2(e0 * inv, e1 * inv);
    }
}

// ---------------- launch ----------------
extern "C" void kernel_launch(void* const* d_in, const int* in_sizes, int n_in,
                              void* d_out, int out_size) {
    const float* x   = (const float*)d_in[0];
    const float* W1  = (const float*)d_in[1];
    const float* b1  = (const float*)d_in[2];
    const float* W2  = (const float*)d_in[3];
    const float* b2  = (const float*)d_in[4];
    const float* Wm1 = (const float*)d_in[5];
    const float* bm1 = (const float*)d_in[6];
    const float* Wm2 = (const float*)d_in[7];
    const float* bm2 = (const float*)d_in[8];
    const int* edges = (const int*)d_in[9];
    const int* tf    = (const int*)d_in[11];
    const int* gene  = (const int*)d_in[12];
    int ne = in_sizes[9] / 2;
    const int* src = edges;
    const int* dst = edges + ne;
    float* out = (float*)d_out;

    const int fused_smem = (128 * 128 + 128 * 64 + 64 * 128 + 64 * 128 + 128) * 4;
    cudaFuncSetAttribute(agg_gemm_kernel, cudaFuncAttributeMaxDynamicSharedMemorySize, fused_smem);
    cudaFuncSetAttribute(pair_kernel, cudaFuncAttributeMaxDynamicSharedMemorySize,
                         (DIM * NT + DIM * 32) * 4 + DIM * 8);

    void *p_At, *p_Bt;
    cudaGetSymbolAddress(&p_At, g_At);
    cudaGetSymbolAddress(&p_Bt, g_Bt);

    const int nb_scan = (NNODES + 1 + 1023) / 1024;  // 79
    int hb = ((ne >> 2) + 255) / 256;
    int combo_blocks = hb + 5000 + (NG + 255) / 256;

    zero_kernel<<<(NNODES + 1 + 255) / 256, 256>>>();
    combo_kernel<<<combo_blocks, 256>>>(x, dst, ne, hb, tf, gene);
    scan1_kernel<<<nb_scan, 1024>>>();
    scan2_kernel<<<1, 32>>>(nb_scan);
    scan3_kernel<<<nb_scan, 1024>>>();
    scatter_kernel<<<((ne >> 2) + 255) / 256, 256>>>(src, dst, ne);
    agg_gemm_kernel<<<NNODES / 64, 512, fused_smem>>>(W1, b1, W2);
    agg2_csr_kernel<<<(NT + NG + 7) / 8, 256>>>();
    half_mlp_kernel<<<NT, 128>>>(tf, NT, Wm1, b2, nullptr, (float*)p_At, NT);
    half_mlp_kernel<<<1000, 128>>>(gene, NG, Wm1 + 64 * DIM, b2, bm1, (float*)p_Bt, NG);
    pair_kernel<<<NG / 32, 256, (DIM * NT + DIM * 32) * 4 + DIM * 8>>>(Wm2, bm2, out);
}

// round 7
// speedup vs baseline: 1.6237x; 1.6237x over previous
#include <cuda_runtime.h>
#include <cuda_fp16.h>
#include <math.h>

#define NNODES 80000
#define DIM    128
#define DEMB   64
#define NT     128
#define NG     8000
#define NUMP   40000
#define NEMAX  2560000
#define PITCH  136   // padded fp16 smem row pitch (bank-conflict-free fragment loads)

typedef unsigned long long ull;

__device__ __forceinline__ ull ffma2(ull a, ull b, ull c) {
    ull d;
    asm("fma.rn.f32x2 %0, %1, %2, %3;" : "=l"(d) : "l"(a), "l"(b), "l"(c));
    return d;
}
__device__ __forceinline__ ull bcast2(float a) {
    ull d;
    asm("mov.b64 %0, {%1, %1};" : "=l"(d) : "f"(a));
    return d;
}
__device__ __forceinline__ float2 unpack2(ull v) {
    float2 f;
    asm("mov.b64 {%0, %1}, %2;" : "=f"(f.x), "=f"(f.y) : "l"(v));
    return f;
}
__device__ __forceinline__ void mma16816(float* d, const unsigned* a, const unsigned* b) {
    asm volatile(
        "mma.sync.aligned.m16n8k16.row.col.f32.f16.f16.f32 "
        "{%0,%1,%2,%3}, {%4,%5,%6,%7}, {%8,%9}, {%0,%1,%2,%3};"
        : "+f"(d[0]), "+f"(d[1]), "+f"(d[2]), "+f"(d[3])
        : "r"(a[0]), "r"(a[1]), "r"(a[2]), "r"(a[3]), "r"(b[0]), "r"(b[1]));
}

// ---------------- scratch (static device arrays; no allocation) ----------------
__device__ int g_rowptr[NNODES + 1];
__device__ int g_cursor[NNODES];
__device__ int g_flag[NNODES];
__device__ int g_list[NT + NG];
__device__ int g_nlist;
__device__ int g_bsum[128];
__device__ int g_esrc[NEMAX];                                  // CSR: src per edge, grouped by dst
__device__ __align__(16) __half g_xh [(size_t)NNODES * DIM];   // fp16 copy of x (agg1 gather src)
__device__ __align__(16) __half g_xah[(size_t)NNODES * DIM];   // agg1 output means, fp16
__device__ __align__(16) __half g_w1t[DIM * DIM];              // W1^T fp16 [n][k]
__device__ __align__(16) __half g_w2t[DEMB * DIM];             // W2^T fp16 [n][k]
__device__ __align__(16) float g_p [(size_t)NNODES * DEMB];    // relu(agg1@W1+b1)@W2
__device__ __align__(16) float g_pa[(size_t)NNODES * DEMB];    // agg2 output (listed rows only)
__device__ __align__(16) float g_At[DIM * NT];                 // A transposed [k][t]
__device__ __align__(16) float g_Bt[(size_t)DIM * NG];         // B transposed [k][g]

// ---------------- zero counters/flags ----------------
__global__ void zero_kernel() {
    int i = blockIdx.x * blockDim.x + threadIdx.x;
    if (i <= NNODES) g_rowptr[i] = 0;
    if (i <  NNODES) g_flag[i] = 0;
    if (i == 0) g_nlist = 0;
}

// ---------------- combo: hist(int4) + x->fp16 + flag/list + W transpose/fp16 ----------------
__global__ void combo_kernel(const float* __restrict__ x,
                             const int* __restrict__ dst, int ne, int hb,
                             const int* __restrict__ tf, const int* __restrict__ gene,
                             const float* __restrict__ W1, const float* __restrict__ W2) {
    int b = blockIdx.x;
    const int fb = (NG + 255) / 256;
    if (b < hb) {                       // histogram, 4 edges/thread
        int i = b * 256 + threadIdx.x;
        int ne4 = ne >> 2;
        if (i < ne4) {
            int4 d4 = reinterpret_cast<const int4*>(dst)[i];
            atomicAdd(&g_rowptr[d4.x + 1], 1);
            atomicAdd(&g_rowptr[d4.y + 1], 1);
            atomicAdd(&g_rowptr[d4.z + 1], 1);
            atomicAdd(&g_rowptr[d4.w + 1], 1);
        }
        if (b == 0 && threadIdx.x == 0) {
            for (int e = ne4 * 4; e < ne; e++) atomicAdd(&g_rowptr[dst[e] + 1], 1);
        }
    } else if (b < hb + 5000) {         // x -> fp16 (one thread per 8 floats)
        int i = (b - hb) * 256 + threadIdx.x;
        if (i < NNODES * DIM / 8) {
            float4 a = reinterpret_cast<const float4*>(x)[2 * i];
            float4 bq = reinterpret_cast<const float4*>(x)[2 * i + 1];
            __half2 h0 = __floats2half2_rn(a.x, a.y);
            __half2 h1 = __floats2half2_rn(a.z, a.w);
            __half2 h2 = __floats2half2_rn(bq.x, bq.y);
            __half2 h3 = __floats2half2_rn(bq.z, bq.w);
            uint4 o;
            o.x = *reinterpret_cast<unsigned*>(&h0);
            o.y = *reinterpret_cast<unsigned*>(&h1);
            o.z = *reinterpret_cast<unsigned*>(&h2);
            o.w = *reinterpret_cast<unsigned*>(&h3);
            reinterpret_cast<uint4*>(g_xh)[i] = o;
        }
    } else if (b < hb + 5000 + fb) {    // flag + compact list
        int i = (b - hb - 5000) * 256 + threadIdx.x;
        if (i < NT) {
            int nd = NUMP + tf[i];
            if (atomicExch(&g_flag[nd], 1) == 0) g_list[atomicAdd(&g_nlist, 1)] = nd;
        }
        if (i < NG) {
            int nd = NUMP + gene[i];
            if (atomicExch(&g_flag[nd], 1) == 0) g_list[atomicAdd(&g_nlist, 1)] = nd;
        }
    } else {                            // W1/W2 transpose -> fp16
        int i = (b - hb - 5000 - fb) * 256 + threadIdx.x;
        if (i < DIM * DIM) {
            int k = i >> 7, n = i & 127;
            g_w1t[n * DIM + k] = __float2half(W1[i]);
        } else if (i < DIM * DIM + DIM * DEMB) {
            int j = i - DIM * DIM;
            int k = j >> 6, n = j & 63;
            g_w2t[n * DIM + k] = __float2half(W2[j]);
        }
    }
}

// ---------------- scan over g_rowptr ----------------
__global__ __launch_bounds__(1024) void scan1_kernel() {
    __shared__ int wsum[32];
    int gid = blockIdx.x * 1024 + threadIdx.x;
    int lane = threadIdx.x & 31, wid = threadIdx.x >> 5;
    int s = (gid <= NNODES) ? g_rowptr[gid] : 0;
#pragma unroll
    for (int o = 1; o < 32; o <<= 1) { int t = __shfl_up_sync(0xffffffffu, s, o); if (lane >= o) s += t; }
    if (lane == 31) wsum[wid] = s;
    __syncthreads();
    if (wid == 0) {
        int w = wsum[lane];
#pragma unroll
        for (int o = 1; o < 32; o <<= 1) { int t = __shfl_up_sync(0xffffffffu, w, o); if (lane >= o) w += t; }
        wsum[lane] = w;
    }
    __syncthreads();
    if (wid > 0) s += wsum[wid - 1];
    if (gid <= NNODES) g_rowptr[gid] = s;
    if (threadIdx.x == 1023) g_bsum[blockIdx.x] = s;
}

__global__ void scan2_kernel(int nb) {
    int lane = threadIdx.x;
    int carry = 0;
    for (int base = 0; base < nb; base += 32) {
        int v = (base + lane < nb) ? g_bsum[base + lane] : 0;
#pragma unroll
        for (int o = 1; o < 32; o <<= 1) { int t = __shfl_up_sync(0xffffffffu, v, o); if (lane >= o) v += t; }
        v += carry;
        if (base + lane < nb) g_bsum[base + lane] = v;
        carry = __shfl_sync(0xffffffffu, v, 31);
    }
}

__global__ __launch_bounds__(1024) void scan3_kernel() {
    int gid = blockIdx.x * 1024 + threadIdx.x;
    if (gid > NNODES) return;
    int v = g_rowptr[gid];
    if (blockIdx.x > 0) v += g_bsum[blockIdx.x - 1];
    g_rowptr[gid] = v;
    if (gid < NNODES) g_cursor[gid] = v;
}

// ---------------- scatter, 4 edges per thread ----------------
__global__ void scatter_kernel(const int* __restrict__ src, const int* __restrict__ dst, int ne) {
    int i = blockIdx.x * blockDim.x + threadIdx.x;
    int ne4 = ne >> 2;
    if (i < ne4) {
        int4 s4 = reinterpret_cast<const int4*>(src)[i];
        int4 d4 = reinterpret_cast<const int4*>(dst)[i];
        g_esrc[atomicAdd(&g_cursor[d4.x], 1)] = s4.x;
        g_esrc[atomicAdd(&g_cursor[d4.y], 1)] = s4.y;
        g_esrc[atomicAdd(&g_cursor[d4.z], 1)] = s4.z;
        g_esrc[atomicAdd(&g_cursor[d4.w], 1)] = s4.w;
    }
    if (i == 0) {
        for (int e = ne4 * 4; e < ne; e++)
            g_esrc[atomicAdd(&g_cursor[dst[e]], 1)] = src[e];
    }
}

// ---------------- agg1: warp per dst, half-warps gather 2 edges (fp16 rows) -> fp16 means -----
__global__ __launch_bounds__(256) void agg1_csr_kernel() {
    int d = blockIdx.x * 8 + (threadIdx.x >> 5);
    if (d >= NNODES) return;
    int lane = threadIdx.x & 31;
    int half = lane >> 4;       // which edge of the pair
    int sub  = lane & 15;       // 16B chunk within 256B row
    int beg = g_rowptr[d], end = g_rowptr[d + 1];
    float acc[8];
#pragma unroll
    for (int k = 0; k < 8; k++) acc[k] = 0.f;

    int j = beg;
    for (; j + 3 < end; j += 4) {
        int s0 = g_esrc[j + half];
        int s1 = g_esrc[j + 2 + half];
        uint4 va = *reinterpret_cast<const uint4*>(g_xh + (size_t)s0 * DIM + sub * 8);
        uint4 vb = *reinterpret_cast<const uint4*>(g_xh + (size_t)s1 * DIM + sub * 8);
        __half2 p0 = __hadd2(*reinterpret_cast<__half2*>(&va.x), *reinterpret_cast<__half2*>(&vb.x));
        __half2 p1 = __hadd2(*reinterpret_cast<__half2*>(&va.y), *reinterpret_cast<__half2*>(&vb.y));
        __half2 p2 = __hadd2(*reinterpret_cast<__half2*>(&va.z), *reinterpret_cast<__half2*>(&vb.z));
        __half2 p3 = __hadd2(*reinterpret_cast<__half2*>(&va.w), *reinterpret_cast<__half2*>(&vb.w));
        float2 f;
        f = __half22float2(p0); acc[0] += f.x; acc[1] += f.y;
        f = __half22float2(p1); acc[2] += f.x; acc[3] += f.y;
        f = __half22float2(p2); acc[4] += f.x; acc[5] += f.y;
        f = __half22float2(p3); acc[6] += f.x; acc[7] += f.y;
    }
    for (; j < end; j += 2) {
        int jj = j + half;
        if (jj < end) {
            int s = g_esrc[jj];
            uint4 v = *reinterpret_cast<const uint4*>(g_xh + (size_t)s * DIM + sub * 8);
            float2 f;
            f = __half22float2(*reinterpret_cast<__half2*>(&v.x)); acc[0] += f.x; acc[1] += f.y;
            f = __half22float2(*reinterpret_cast<__half2*>(&v.y)); acc[2] += f.x; acc[3] += f.y;
            f = __half22float2(*reinterpret_cast<__half2*>(&v.z)); acc[4] += f.x; acc[5] += f.y;
            f = __half22float2(*reinterpret_cast<__half2*>(&v.w)); acc[6] += f.x; acc[7] += f.y;
        }
    }
#pragma unroll
    for (int k = 0; k < 8; k++) acc[k] += __shfl_xor_sync(0xffffffffu, acc[k], 16);
    if (half == 0) {
        float inv = 1.f / fmaxf((float)(end - beg), 1.f);
        __half2 h0 = __floats2half2_rn(acc[0] * inv, acc[1] * inv);
        __half2 h1 = __floats2half2_rn(acc[2] * inv, acc[3] * inv);
        __half2 h2 = __floats2half2_rn(acc[4] * inv, acc[5] * inv);
        __half2 h3 = __floats2half2_rn(acc[6] * inv, acc[7] * inv);
        uint4 o;
        o.x = *reinterpret_cast<unsigned*>(&h0);
        o.y = *reinterpret_cast<unsigned*>(&h1);
        o.z = *reinterpret_cast<unsigned*>(&h2);
        o.w = *reinterpret_cast<unsigned*>(&h3);
        *reinterpret_cast<uint4*>(g_xah + (size_t)d * DIM + sub * 8) = o;
    }
}

// ---------------- HMMA GEMM: p = relu(xah @ W1 + b1) @ W2  (64 rows/block, 512 thr) ----------
__global__ __launch_bounds__(512) void hmma_gemm_kernel(const float* __restrict__ b1) {
    extern __shared__ __half hsm[];
    __half* W1s = hsm;                    // 128 x PITCH
    __half* W2s = W1s + 128 * PITCH;      // 64 x PITCH
    __half* Is  = W2s + 64 * PITCH;       // 64 x PITCH
    __half* Hs  = Is  + 64 * PITCH;       // 64 x PITCH
    float*  b1s = reinterpret_cast<float*>(Hs + 64 * PITCH);  // 128 floats
    int tid = threadIdx.x;
    int row0 = blockIdx.x * 64;  // 1250 * 64 = 80000 exact

    // fill smem (uint4 = 8 halves; PITCH*2 = 272 bytes, 16B-aligned per row)
    for (int i = tid; i < 128 * 16; i += 512) {
        int n = i >> 4, ch = i & 15;
        reinterpret_cast<uint4*>(W1s + n * PITCH)[ch] =
            reinterpret_cast<const uint4*>(g_w1t + n * DIM)[ch];
    }
    for (int i = tid; i < 64 * 16; i += 512) {
        int n = i >> 4, ch = i & 15;
        reinterpret_cast<uint4*>(W2s + n * PITCH)[ch] =
            reinterpret_cast<const uint4*>(g_w2t + n * DIM)[ch];
    }
    for (int i = tid; i < 64 * 16; i += 512) {
        int r = i >> 4, ch = i & 15;
        reinterpret_cast<uint4*>(Is + r * PITCH)[ch] =
            reinterpret_cast<const uint4*>(g_xah + (size_t)(row0 + r) * DIM)[ch];
    }
    if (tid < 128) b1s[tid] = b1[tid];
    __syncthreads();

    int warp = tid >> 5, lane = tid & 31;
    int g = lane >> 2, c = lane & 3;

    // phase 1: H(64x128) = relu(Is @ W1^T-frag + b1) ; warp tile 16x32
    {
        int r0 = (warp & 3) * 16, c0 = (warp >> 2) * 32;
        float d[4][4];
#pragma unroll
        for (int nt = 0; nt < 4; nt++)
#pragma unroll
            for (int q = 0; q < 4; q++) d[nt][q] = 0.f;

#pragma unroll
        for (int k0 = 0; k0 < 128; k0 += 16) {
            unsigned a[4];
            const __half* ip = Is + (r0 + g) * PITCH + k0 + 2 * c;
            a[0] = *reinterpret_cast<const unsigned*>(ip);
            a[1] = *reinterpret_cast<const unsigned*>(ip + 8 * PITCH);
            a[2] = *reinterpret_cast<const unsigned*>(ip + 8);
            a[3] = *reinterpret_cast<const unsigned*>(ip + 8 * PITCH + 8);
#pragma unroll
            for (int nt = 0; nt < 4; nt++) {
                const __half* wp = W1s + (c0 + nt * 8 + g) * PITCH + k0 + 2 * c;
                unsigned bb[2];
                bb[0] = *reinterpret_cast<const unsigned*>(wp);
                bb[1] = *reinterpret_cast<const unsigned*>(wp + 8);
                mma16816(d[nt], a, bb);
            }
        }
#pragma unroll
        for (int nt = 0; nt < 4; nt++) {
            int col = c0 + nt * 8 + 2 * c;
            float bx = b1s[col], by = b1s[col + 1];
            __half2 lo = __floats2half2_rn(fmaxf(d[nt][0] + bx, 0.f), fmaxf(d[nt][1] + by, 0.f));
            __half2 hi = __floats2half2_rn(fmaxf(d[nt][2] + bx, 0.f), fmaxf(d[nt][3] + by, 0.f));
            *reinterpret_cast<__half2*>(Hs + (r0 + g) * PITCH + col) = lo;
            *reinterpret_cast<__half2*>(Hs + (r0 + g + 8) * PITCH + col) = hi;
        }
    }
    __syncthreads();

    // phase 2: P(64x64) = Hs @ W2 ; warp tile 16x16
    {
        int r0 = (warp & 3) * 16, c0 = (warp >> 2) * 16;
        float d[2][4];
#pragma unroll
        for (int nt = 0; nt < 2; nt++)
#pragma unroll
            for (int q = 0; q < 4; q++) d[nt][q] = 0.f;

#pragma unroll
        for (int k0 = 0; k0 < 128; k0 += 16) {
            unsigned a[4];
            const __half* hp = Hs + (r0 + g) * PITCH + k0 + 2 * c;
            a[0] = *reinterpret_cast<const unsigned*>(hp);
            a[1] = *reinterpret_cast<const unsigned*>(hp + 8 * PITCH);
            a[2] = *reinterpret_cast<const unsigned*>(hp + 8);
            a[3] = *reinterpret_cast<const unsigned*>(hp + 8 * PITCH + 8);
#pragma unroll
            for (int nt = 0; nt < 2; nt++) {
                const __half* wp = W2s + (c0 + nt * 8 + g) * PITCH + k0 + 2 * c;
                unsigned bb[2];
                bb[0] = *reinterpret_cast<const unsigned*>(wp);
                bb[1] = *reinterpret_cast<const unsigned*>(wp + 8);
                mma16816(d[nt], a, bb);
            }
        }
#pragma unroll
        for (int nt = 0; nt < 2; nt++) {
            int col = c0 + nt * 8 + 2 * c;
            int row = row0 + r0 + g;
            *reinterpret_cast<float2*>(g_p + (size_t)row * DEMB + col) = make_float2(d[nt][0], d[nt][1]);
            *reinterpret_cast<float2*>(g_p + (size_t)(row + 8) * DEMB + col) = make_float2(d[nt][2], d[nt][3]);
        }
    }
}

// ---------------- agg2: warp per listed dst, half-warps gather 2 edges (fp32 rows, 256B) --------
__global__ __launch_bounds__(256) void agg2_csr_kernel() {
    int idx = blockIdx.x * 8 + (threadIdx.x >> 5);
    if (idx >= g_nlist) return;
    int d = g_list[idx];
    int lane = threadIdx.x & 31;
    int half = lane >> 4;
    int sub  = lane & 15;       // 16B chunk within 256B row (4 floats)
    int beg = g_rowptr[d], end = g_rowptr[d + 1];
    float acc[4] = {0.f, 0.f, 0.f, 0.f};

    int j = beg;
    for (; j + 3 < end; j += 4) {
        int s0 = g_esrc[j + half];
        int s1 = g_esrc[j + 2 + half];
        float4 va = *reinterpret_cast<const float4*>(g_p + (size_t)s0 * DEMB + sub * 4);
        float4 vb = *reinterpret_cast<const float4*>(g_p + (size_t)s1 * DEMB + sub * 4);
        acc[0] += va.x + vb.x; acc[1] += va.y + vb.y;
        acc[2] += va.z + vb.z; acc[3] += va.w + vb.w;
    }
    for (; j < end; j += 2) {
        int jj = j + half;
        if (jj < end) {
            int s = g_esrc[jj];
            float4 v = *reinterpret_cast<const float4*>(g_p + (size_t)s * DEMB + sub * 4);
            acc[0] += v.x; acc[1] += v.y; acc[2] += v.z; acc[3] += v.w;
        }
    }
#pragma unroll
    for (int k = 0; k < 4; k++) acc[k] += __shfl_xor_sync(0xffffffffu, acc[k], 16);
    if (half == 0) {
        float inv = 1.f / fmaxf((float)(end - beg), 1.f);
        reinterpret_cast<float4*>(g_pa + (size_t)d * DEMB + sub * 4)[0] =
            make_float4(acc[0] * inv, acc[1] * inv, acc[2] * inv, acc[3] * inv);
    }
}

// ---------------- half-MLP: OutT[k][r] = sum_d (pa[node_r][d] + b2[d]) * Whalf[d][k] (+bm1[k]) ------
__global__ __launch_bounds__(128) void half_mlp_kernel(
    const int* __restrict__ list, int nrows,
    const float* __restrict__ Whalf, const float* __restrict__ b2,
    const float* __restrict__ bm1, float* __restrict__ OutT, int ldo) {
    __shared__ __align__(8) float Wst[128 * 66];   // transposed [t][d], pad 66 (even) for ull loads
    __shared__ __align__(8) float es[DEMB];
    int tid = threadIdx.x;  // 128 (= t)

#pragma unroll 4
    for (int d = 0; d < DEMB; d++) Wst[tid * 66 + d] = Whalf[d * DIM + tid];
    float base = bm1 ? bm1[tid] : 0.f;

    for (int r = blockIdx.x; r < nrows; r += gridDim.x) {
        __syncthreads();
        if (tid < DEMB) {
            int node = NUMP + list[r];
            es[tid] = g_pa[(size_t)node * DEMB + tid] + b2[tid];
        }
        __syncthreads();
        ull acc = 0ull;
#pragma unroll 8
        for (int d = 0; d < DEMB; d += 2) {
            ull ep = *reinterpret_cast<const ull*>(es + d);
            ull wp = *reinterpret_cast<const ull*>(Wst + tid * 66 + d);
            acc = ffma2(ep, wp, acc);
        }
        float2 a2 = unpack2(acc);
        OutT[(size_t)tid * ldo + r] = base + a2.x + a2.y;
    }
}

// ---------------- pair kernel: out[t*NG+g] = softmax( relu(A[t]+B[g]) @ Wm2 + bm2 ) ----------------
__global__ __launch_bounds__(256) void pair_kernel(
    const float* __restrict__ Wm2, const float* __restrict__ bm2, float* __restrict__ out) {
    extern __shared__ float sm[];
    float* As = sm;                       // [k][t] 128*128
    float* Bs = sm + DIM * NT;            // [k][gl] 128*32
    float2* w2 = reinterpret_cast<float2*>(sm + DIM * NT + DIM * 32);
    int tid = threadIdx.x;  // 256

    for (int i = tid; i < DIM * NT / 4; i += 256)
        reinterpret_cast<float4*>(As)[i] = reinterpret_cast<const float4*>(g_At)[i];
    int g0 = blockIdx.x * 32;
    for (int i = tid; i < DIM * 32; i += 256) {
        int k = i >> 5, gl = i & 31;
        Bs[i] = g_Bt[(size_t)k * NG + g0 + gl];
    }
    if (tid < DIM) w2[tid] = reinterpret_cast<const float2*>(Wm2)[tid];
    __syncthreads();

    float bo0 = bm2[0], bo1 = bm2[1];
    int lane = tid & 31, warp = tid >> 5;
    ull accp[16];
#pragma unroll
    for (int i = 0; i < 16; i++) accp[i] = 0ull;

#pragma unroll 4
    for (int k = 0; k < DIM; k++) {
        float bv = Bs[k * 32 + lane];
        ull wp = *reinterpret_cast<const ull*>(&w2[k]);
#pragma unroll
        for (int i = 0; i < 16; i++) {
            float a = As[k * DIM + warp + 8 * i];
            float v = fmaxf(a + bv, 0.f);
            accp[i] = ffma2(bcast2(v), wp, accp[i]);
        }
    }

#pragma unroll
    for (int i = 0; i < 16; i++) {
        int t = warp + 8 * i;
        float2 a2 = unpack2(accp[i]);
        float o0 = a2.x + bo0, o1 = a2.y + bo1;
        float m  = fmaxf(o0, o1);
        float e0 = __expf(o0 - m), e1 = __expf(o1 - m);
        float inv = 1.f / (e0 + e1);
        reinterpret_cast<float2*>(out)[(size_t)t * NG + g0 + lane] = make_float2(e0 * inv, e1 * inv);
    }
}

// ---------------- launch ----------------
extern "C" void kernel_launch(void* const* d_in, const int* in_sizes, int n_in,
                              void* d_out, int out_size) {
    const float* x   = (const float*)d_in[0];
    const float* W1  = (const float*)d_in[1];
    const float* b1  = (const float*)d_in[2];
    const float* W2  = (const float*)d_in[3];
    const float* b2  = (const float*)d_in[4];
    const float* Wm1 = (const float*)d_in[5];
    const float* bm1 = (const float*)d_in[6];
    const float* Wm2 = (const float*)d_in[7];
    const float* bm2 = (const float*)d_in[8];
    const int* edges = (const int*)d_in[9];
    const int* tf    = (const int*)d_in[11];
    const int* gene  = (const int*)d_in[12];
    int ne = in_sizes[9] / 2;
    const int* src = edges;
    const int* dst = edges + ne;
    float* out = (float*)d_out;

    const int gemm_smem = (128 + 64 + 64 + 64) * PITCH * 2 + 128 * 4;  // ~87.5 KB
    cudaFuncSetAttribute(hmma_gemm_kernel, cudaFuncAttributeMaxDynamicSharedMemorySize, gemm_smem);
    cudaFuncSetAttribute(pair_kernel, cudaFuncAttributeMaxDynamicSharedMemorySize,
                         (DIM * NT + DIM * 32) * 4 + DIM * 8);

    void *p_At, *p_Bt;
    cudaGetSymbolAddress(&p_At, g_At);
    cudaGetSymbolAddress(&p_Bt, g_Bt);

    const int nb_scan = (NNODES + 1 + 1023) / 1024;  // 79
    int hb = ((ne >> 2) + 255) / 256;
    int fb = (NG + 255) / 256;
    int tb = (DIM * DIM + DIM * DEMB + 255) / 256;   // 96
    int combo_blocks = hb + 5000 + fb + tb;

    zero_kernel<<<(NNODES + 1 + 255) / 256, 256>>>();
    combo_kernel<<<combo_blocks, 256>>>(x, dst, ne, hb, tf, gene, W1, W2);
    scan1_kernel<<<nb_scan, 1024>>>();
    scan2_kernel<<<1, 32>>>(nb_scan);
    scan3_kernel<<<nb_scan, 1024>>>();
    scatter_kernel<<<((ne >> 2) + 255) / 256, 256>>>(src, dst, ne);
    agg1_csr_kernel<<<NNODES / 8, 256>>>();
    hmma_gemm_kernel<<<NNODES / 64, 512, gemm_smem>>>(b1);
    agg2_csr_kernel<<<(NT + NG + 7) / 8, 256>>>();
    half_mlp_kernel<<<NT, 128>>>(tf, NT, Wm1, b2, nullptr, (float*)p_At, NT);
    half_mlp_kernel<<<1000, 128>>>(gene, NG, Wm1 + 64 * DIM, b2, bm1, (float*)p_Bt, NG);
    pair_kernel<<<NG / 32, 256, (DIM * NT + DIM * 32) * 4 + DIM * 8>>>(Wm2, bm2, out);
}

// round 8
// speedup vs baseline: 1.6587x; 1.0215x over previous
#include <cuda_runtime.h>
#include <cuda_fp16.h>
#include <math.h>

#define NNODES 80000
#define DIM    128
#define DEMB   64
#define NT     128
#define NG     8000
#define NUMP   40000
#define NEMAX  2560000
#define PITCH  136   // padded fp16 smem row pitch (bank-conflict-free fragment loads)

typedef unsigned long long ull;

__device__ __forceinline__ ull ffma2(ull a, ull b, ull c) {
    ull d;
    asm("fma.rn.f32x2 %0, %1, %2, %3;" : "=l"(d) : "l"(a), "l"(b), "l"(c));
    return d;
}
__device__ __forceinline__ ull bcast2(float a) {
    ull d;
    asm("mov.b64 %0, {%1, %1};" : "=l"(d) : "f"(a));
    return d;
}
__device__ __forceinline__ float2 unpack2(ull v) {
    float2 f;
    asm("mov.b64 {%0, %1}, %2;" : "=f"(f.x), "=f"(f.y) : "l"(v));
    return f;
}
__device__ __forceinline__ void mma16816(float* d, const unsigned* a, const unsigned* b) {
    asm volatile(
        "mma.sync.aligned.m16n8k16.row.col.f32.f16.f16.f32 "
        "{%0,%1,%2,%3}, {%4,%5,%6,%7}, {%8,%9}, {%0,%1,%2,%3};"
        : "+f"(d[0]), "+f"(d[1]), "+f"(d[2]), "+f"(d[3])
        : "r"(a[0]), "r"(a[1]), "r"(a[2]), "r"(a[3]), "r"(b[0]), "r"(b[1]));
}

// ---------------- scratch (static device arrays; no allocation) ----------------
__device__ int g_rowptr[NNODES + 1];
__device__ int g_flag[NNODES];
__device__ int g_list[NT + NG];
__device__ int g_nlist;
__device__ int g_bsum[128];
__device__ int g_rank[NEMAX];                                  // per-edge rank within dst
__device__ int g_esrc[NEMAX];                                  // CSR: src per edge, grouped by dst
__device__ __align__(16) __half g_xh [(size_t)NNODES * DIM];   // fp16 copy of x (agg1 gather src)
__device__ __align__(16) __half g_xah[(size_t)NNODES * DIM];   // agg1 output means, fp16
__device__ __align__(16) __half g_w1t[DIM * DIM];              // W1^T fp16 [n][k]
__device__ __align__(16) __half g_w2t[DEMB * DIM];             // W2^T fp16 [n][k]
__device__ __align__(16) __half g_ph[(size_t)NNODES * DEMB];   // relu(agg1@W1+b1)@W2, fp16
__device__ __align__(16) float g_pa[(size_t)NNODES * DEMB];    // agg2 output (listed rows only)
__device__ __align__(16) float g_At[DIM * NT];                 // A transposed [k][t]
__device__ __align__(16) float g_Bt[(size_t)DIM * NG];         // B transposed [k][g]

// ---------------- zero counters/flags ----------------
__global__ void zero_kernel() {
    int i = blockIdx.x * blockDim.x + threadIdx.x;
    if (i <= NNODES) g_rowptr[i] = 0;
    if (i <  NNODES) g_flag[i] = 0;
    if (i == 0) g_nlist = 0;
}

// ---------------- combo: hist+rank(int4) + x->fp16 + flag/list + W transpose/fp16 ----------------
__global__ void combo_kernel(const float* __restrict__ x,
                             const int* __restrict__ dst, int ne, int hb,
                             const int* __restrict__ tf, const int* __restrict__ gene,
                             const float* __restrict__ W1, const float* __restrict__ W2) {
    int b = blockIdx.x;
    const int fb = (NG + 255) / 256;
    if (b < hb) {                       // histogram + rank, 4 edges/thread
        int i = b * 256 + threadIdx.x;
        int ne4 = ne >> 2;
        if (i < ne4) {
            int4 d4 = reinterpret_cast<const int4*>(dst)[i];
            int4 r4;
            r4.x = atomicAdd(&g_rowptr[d4.x + 1], 1);
            r4.y = atomicAdd(&g_rowptr[d4.y + 1], 1);
            r4.z = atomicAdd(&g_rowptr[d4.z + 1], 1);
            r4.w = atomicAdd(&g_rowptr[d4.w + 1], 1);
            reinterpret_cast<int4*>(g_rank)[i] = r4;
        }
        if (b == 0 && threadIdx.x == 0) {
            for (int e = ne4 * 4; e < ne; e++)
                g_rank[e] = atomicAdd(&g_rowptr[dst[e] + 1], 1);
        }
    } else if (b < hb + 5000) {         // x -> fp16 (one thread per 8 floats)
        int i = (b - hb) * 256 + threadIdx.x;
        if (i < NNODES * DIM / 8) {
            float4 a = reinterpret_cast<const float4*>(x)[2 * i];
            float4 bq = reinterpret_cast<const float4*>(x)[2 * i + 1];
            __half2 h0 = __floats2half2_rn(a.x, a.y);
            __half2 h1 = __floats2half2_rn(a.z, a.w);
            __half2 h2 = __floats2half2_rn(bq.x, bq.y);
            __half2 h3 = __floats2half2_rn(bq.z, bq.w);
            uint4 o;
            o.x = *reinterpret_cast<unsigned*>(&h0);
            o.y = *reinterpret_cast<unsigned*>(&h1);
            o.z = *reinterpret_cast<unsigned*>(&h2);
            o.w = *reinterpret_cast<unsigned*>(&h3);
            reinterpret_cast<uint4*>(g_xh)[i] = o;
        }
    } else if (b < hb + 5000 + fb) {    // flag + compact list
        int i = (b - hb - 5000) * 256 + threadIdx.x;
        if (i < NT) {
            int nd = NUMP + tf[i];
            if (atomicExch(&g_flag[nd], 1) == 0) g_list[atomicAdd(&g_nlist, 1)] = nd;
        }
        if (i < NG) {
            int nd = NUMP + gene[i];
            if (atomicExch(&g_flag[nd], 1) == 0) g_list[atomicAdd(&g_nlist, 1)] = nd;
        }
    } else {                            // W1/W2 transpose -> fp16
        int i = (b - hb - 5000 - fb) * 256 + threadIdx.x;
        if (i < DIM * DIM) {
            int k = i >> 7, n = i & 127;
            g_w1t[n * DIM + k] = __float2half(W1[i]);
        } else if (i < DIM * DIM + DIM * DEMB) {
            int j = i - DIM * DIM;
            int k = j >> 6, n = j & 63;
            g_w2t[n * DIM + k] = __float2half(W2[j]);
        }
    }
}

// ---------------- scan over g_rowptr ----------------
__global__ __launch_bounds__(1024) void scan1_kernel() {
    __shared__ int wsum[32];
    int gid = blockIdx.x * 1024 + threadIdx.x;
    int lane = threadIdx.x & 31, wid = threadIdx.x >> 5;
    int s = (gid <= NNODES) ? g_rowptr[gid] : 0;
#pragma unroll
    for (int o = 1; o < 32; o <<= 1) { int t = __shfl_up_sync(0xffffffffu, s, o); if (lane >= o) s += t; }
    if (lane == 31) wsum[wid] = s;
    __syncthreads();
    if (wid == 0) {
        int w = wsum[lane];
#pragma unroll
        for (int o = 1; o < 32; o <<= 1) { int t = __shfl_up_sync(0xffffffffu, w, o); if (lane >= o) w += t; }
        wsum[lane] = w;
    }
    __syncthreads();
    if (wid > 0) s += wsum[wid - 1];
    if (gid <= NNODES) g_rowptr[gid] = s;
    if (threadIdx.x == 1023) g_bsum[blockIdx.x] = s;
}

__global__ void scan2_kernel(int nb) {
    int lane = threadIdx.x;
    int carry = 0;
    for (int base = 0; base < nb; base += 32) {
        int v = (base + lane < nb) ? g_bsum[base + lane] : 0;
#pragma unroll
        for (int o = 1; o < 32; o <<= 1) { int t = __shfl_up_sync(0xffffffffu, v, o); if (lane >= o) v += t; }
        v += carry;
        if (base + lane < nb) g_bsum[base + lane] = v;
        carry = __shfl_sync(0xffffffffu, v, 31);
    }
}

__global__ __launch_bounds__(1024) void scan3_kernel() {
    int gid = blockIdx.x * 1024 + threadIdx.x;
    if (gid > NNODES) return;
    int v = g_rowptr[gid];
    if (blockIdx.x > 0) v += g_bsum[blockIdx.x - 1];
    g_rowptr[gid] = v;
}

// ---------------- scatter (atomic-free): esrc[rowptr[d] + rank[e]] = src[e] ----------------
__global__ void scatter_kernel(const int* __restrict__ src, const int* __restrict__ dst, int ne) {
    int i = blockIdx.x * blockDim.x + threadIdx.x;
    int ne4 = ne >> 2;
    if (i < ne4) {
        int4 s4 = reinterpret_cast<const int4*>(src)[i];
        int4 d4 = reinterpret_cast<const int4*>(dst)[i];
        int4 r4 = reinterpret_cast<const int4*>(g_rank)[i];
        g_esrc[g_rowptr[d4.x] + r4.x] = s4.x;
        g_esrc[g_rowptr[d4.y] + r4.y] = s4.y;
        g_esrc[g_rowptr[d4.z] + r4.z] = s4.z;
        g_esrc[g_rowptr[d4.w] + r4.w] = s4.w;
    }
    if (i == 0) {
        for (int e = ne4 * 4; e < ne; e++)
            g_esrc[g_rowptr[dst[e]] + g_rank[e]] = src[e];
    }
}

// ---------------- agg1: warp per dst, half-warps gather 2 edges (fp16 rows) -> fp16 means -----
__global__ __launch_bounds__(256) void agg1_csr_kernel() {
    int d = blockIdx.x * 8 + (threadIdx.x >> 5);
    if (d >= NNODES) return;
    int lane = threadIdx.x & 31;
    int half = lane >> 4;       // which edge of the pair
    int sub  = lane & 15;       // 16B chunk within 256B row
    int beg = g_rowptr[d], end = g_rowptr[d + 1];
    float acc[8];
#pragma unroll
    for (int k = 0; k < 8; k++) acc[k] = 0.f;

    int j = beg;
    for (; j + 3 < end; j += 4) {
        int s0 = g_esrc[j + half];
        int s1 = g_esrc[j + 2 + half];
        uint4 va = *reinterpret_cast<const uint4*>(g_xh + (size_t)s0 * DIM + sub * 8);
        uint4 vb = *reinterpret_cast<const uint4*>(g_xh + (size_t)s1 * DIM + sub * 8);
        __half2 p0 = __hadd2(*reinterpret_cast<__half2*>(&va.x), *reinterpret_cast<__half2*>(&vb.x));
        __half2 p1 = __hadd2(*reinterpret_cast<__half2*>(&va.y), *reinterpret_cast<__half2*>(&vb.y));
        __half2 p2 = __hadd2(*reinterpret_cast<__half2*>(&va.z), *reinterpret_cast<__half2*>(&vb.z));
        __half2 p3 = __hadd2(*reinterpret_cast<__half2*>(&va.w), *reinterpret_cast<__half2*>(&vb.w));
        float2 f;
        f = __half22float2(p0); acc[0] += f.x; acc[1] += f.y;
        f = __half22float2(p1); acc[2] += f.x; acc[3] += f.y;
        f = __half22float2(p2); acc[4] += f.x; acc[5] += f.y;
        f = __half22float2(p3); acc[6] += f.x; acc[7] += f.y;
    }
    for (; j < end; j += 2) {
        int jj = j + half;
        if (jj < end) {
            int s = g_esrc[jj];
            uint4 v = *reinterpret_cast<const uint4*>(g_xh + (size_t)s * DIM + sub * 8);
            float2 f;
            f = __half22float2(*reinterpret_cast<__half2*>(&v.x)); acc[0] += f.x; acc[1] += f.y;
            f = __half22float2(*reinterpret_cast<__half2*>(&v.y)); acc[2] += f.x; acc[3] += f.y;
            f = __half22float2(*reinterpret_cast<__half2*>(&v.z)); acc[4] += f.x; acc[5] += f.y;
            f = __half22float2(*reinterpret_cast<__half2*>(&v.w)); acc[6] += f.x; acc[7] += f.y;
        }
    }
#pragma unroll
    for (int k = 0; k < 8; k++) acc[k] += __shfl_xor_sync(0xffffffffu, acc[k], 16);
    if (half == 0) {
        float inv = 1.f / fmaxf((float)(end - beg), 1.f);
        __half2 h0 = __floats2half2_rn(acc[0] * inv, acc[1] * inv);
        __half2 h1 = __floats2half2_rn(acc[2] * inv, acc[3] * inv);
        __half2 h2 = __floats2half2_rn(acc[4] * inv, acc[5] * inv);
        __half2 h3 = __floats2half2_rn(acc[6] * inv, acc[7] * inv);
        uint4 o;
        o.x = *reinterpret_cast<unsigned*>(&h0);
        o.y = *reinterpret_cast<unsigned*>(&h1);
        o.z = *reinterpret_cast<unsigned*>(&h2);
        o.w = *reinterpret_cast<unsigned*>(&h3);
        *reinterpret_cast<uint4*>(g_xah + (size_t)d * DIM + sub * 8) = o;
    }
}

// ---------------- HMMA GEMM: ph = relu(xah @ W1 + b1) @ W2  (64 rows/block, 512 thr) ----------
__global__ __launch_bounds__(512) void hmma_gemm_kernel(const float* __restrict__ b1) {
    extern __shared__ __half hsm[];
    __half* W1s = hsm;                    // 128 x PITCH
    __half* W2s = W1s + 128 * PITCH;      // 64 x PITCH
    __half* Is  = W2s + 64 * PITCH;       // 64 x PITCH
    __half* Hs  = Is  + 64 * PITCH;       // 64 x PITCH
    float*  b1s = reinterpret_cast<float*>(Hs + 64 * PITCH);  // 128 floats
    int tid = threadIdx.x;
    int row0 = blockIdx.x * 64;  // 1250 * 64 = 80000 exact

    for (int i = tid; i < 128 * 16; i += 512) {
        int n = i >> 4, ch = i & 15;
        reinterpret_cast<uint4*>(W1s + n * PITCH)[ch] =
            reinterpret_cast<const uint4*>(g_w1t + n * DIM)[ch];
    }
    for (int i = tid; i < 64 * 16; i += 512) {
        int n = i >> 4, ch = i & 15;
        reinterpret_cast<uint4*>(W2s + n * PITCH)[ch] =
            reinterpret_cast<const uint4*>(g_w2t + n * DIM)[ch];
    }
    for (int i = tid; i < 64 * 16; i += 512) {
        int r = i >> 4, ch = i & 15;
        reinterpret_cast<uint4*>(Is + r * PITCH)[ch] =
            reinterpret_cast<const uint4*>(g_xah + (size_t)(row0 + r) * DIM)[ch];
    }
    if (tid < 128) b1s[tid] = b1[tid];
    __syncthreads();

    int warp = tid >> 5, lane = tid & 31;
    int g = lane >> 2, c = lane & 3;

    // phase 1: H(64x128) = relu(Is @ W1^T-frag + b1) ; warp tile 16x32
    {
        int r0 = (warp & 3) * 16, c0 = (warp >> 2) * 32;
        float d[4][4];
#pragma unroll
        for (int nt = 0; nt < 4; nt++)
#pragma unroll
            for (int q = 0; q < 4; q++) d[nt][q] = 0.f;

#pragma unroll
        for (int k0 = 0; k0 < 128; k0 += 16) {
            unsigned a[4];
            const __half* ip = Is + (r0 + g) * PITCH + k0 + 2 * c;
            a[0] = *reinterpret_cast<const unsigned*>(ip);
            a[1] = *reinterpret_cast<const unsigned*>(ip + 8 * PITCH);
            a[2] = *reinterpret_cast<const unsigned*>(ip + 8);
            a[3] = *reinterpret_cast<const unsigned*>(ip + 8 * PITCH + 8);
#pragma unroll
            for (int nt = 0; nt < 4; nt++) {
                const __half* wp = W1s + (c0 + nt * 8 + g) * PITCH + k0 + 2 * c;
                unsigned bb[2];
                bb[0] = *reinterpret_cast<const unsigned*>(wp);
                bb[1] = *reinterpret_cast<const unsigned*>(wp + 8);
                mma16816(d[nt], a, bb);
            }
        }
#pragma unroll
        for (int nt = 0; nt < 4; nt++) {
            int col = c0 + nt * 8 + 2 * c;
            float bx = b1s[col], by = b1s[col + 1];
            __half2 lo = __floats2half2_rn(fmaxf(d[nt][0] + bx, 0.f), fmaxf(d[nt][1] + by, 0.f));
            __half2 hi = __floats2half2_rn(fmaxf(d[nt][2] + bx, 0.f), fmaxf(d[nt][3] + by, 0.f));
            *reinterpret_cast<__half2*>(Hs + (r0 + g) * PITCH + col) = lo;
            *reinterpret_cast<__half2*>(Hs + (r0 + g + 8) * PITCH + col) = hi;
        }
    }
    __syncthreads();

    // phase 2: P(64x64) = Hs @ W2 ; warp tile 16x16, fp16 output
    {
        int r0 = (warp & 3) * 16, c0 = (warp >> 2) * 16;
        float d[2][4];
#pragma unroll
        for (int nt = 0; nt < 2; nt++)
#pragma unroll
            for (int q = 0; q < 4; q++) d[nt][q] = 0.f;

#pragma unroll
        for (int k0 = 0; k0 < 128; k0 += 16) {
            unsigned a[4];
            const __half* hp = Hs + (r0 + g) * PITCH + k0 + 2 * c;
            a[0] = *reinterpret_cast<const unsigned*>(hp);
            a[1] = *reinterpret_cast<const unsigned*>(hp + 8 * PITCH);
            a[2] = *reinterpret_cast<const unsigned*>(hp + 8);
            a[3] = *reinterpret_cast<const unsigned*>(hp + 8 * PITCH + 8);
#pragma unroll
            for (int nt = 0; nt < 2; nt++) {
                const __half* wp = W2s + (c0 + nt * 8 + g) * PITCH + k0 + 2 * c;
                unsigned bb[2];
                bb[0] = *reinterpret_cast<const unsigned*>(wp);
                bb[1] = *reinterpret_cast<const unsigned*>(wp + 8);
                mma16816(d[nt], a, bb);
            }
        }
#pragma unroll
        for (int nt = 0; nt < 2; nt++) {
            int col = c0 + nt * 8 + 2 * c;
            int row = row0 + r0 + g;
            __half2 lo = __floats2half2_rn(d[nt][0], d[nt][1]);
            __half2 hi = __floats2half2_rn(d[nt][2], d[nt][3]);
            *reinterpret_cast<__half2*>(g_ph + (size_t)row * DEMB + col) = lo;
            *reinterpret_cast<__half2*>(g_ph + (size_t)(row + 8) * DEMB + col) = hi;
        }
    }
}

// ---------------- agg2: warp per listed dst, quarter-warps gather 4 edges (fp16 rows, 128B) -----
__global__ __launch_bounds__(256) void agg2_csr_kernel() {
    int idx = blockIdx.x * 8 + (threadIdx.x >> 5);
    if (idx >= g_nlist) return;
    int d = g_list[idx];
    int lane = threadIdx.x & 31;
    int q   = lane >> 3;        // which edge of the quad
    int sub = lane & 7;         // 16B chunk within 128B fp16 row
    int beg = g_rowptr[d], end = g_rowptr[d + 1];
    float acc[8];
#pragma unroll
    for (int k = 0; k < 8; k++) acc[k] = 0.f;

    int j = beg;
    for (; j + 3 < end; j += 4) {
        int s = g_esrc[j + q];
        uint4 v = *reinterpret_cast<const uint4*>(g_ph + (size_t)s * DEMB + sub * 8);
        float2 f;
        f = __half22float2(*reinterpret_cast<__half2*>(&v.x)); acc[0] += f.x; acc[1] += f.y;
        f = __half22float2(*reinterpret_cast<__half2*>(&v.y)); acc[2] += f.x; acc[3] += f.y;
        f = __half22float2(*reinterpret_cast<__half2*>(&v.z)); acc[4] += f.x; acc[5] += f.y;
        f = __half22float2(*reinterpret_cast<__half2*>(&v.w)); acc[6] += f.x; acc[7] += f.y;
    }
    if (j + q < end) {
        int s = g_esrc[j + q];
        uint4 v = *reinterpret_cast<const uint4*>(g_ph + (size_t)s * DEMB + sub * 8);
        float2 f;
        f = __half22float2(*reinterpret_cast<__half2*>(&v.x)); acc[0] += f.x; acc[1] += f.y;
        f = __half22float2(*reinterpret_cast<__half2*>(&v.y)); acc[2] += f.x; acc[3] += f.y;
        f = __half22float2(*reinterpret_cast<__half2*>(&v.z)); acc[4] += f.x; acc[5] += f.y;
        f = __half22float2(*reinterpret_cast<__half2*>(&v.w)); acc[6] += f.x; acc[7] += f.y;
    }
#pragma unroll
    for (int k = 0; k < 8; k++) {
        acc[k] += __shfl_xor_sync(0xffffffffu, acc[k], 8);
        acc[k] += __shfl_xor_sync(0xffffffffu, acc[k], 16);
    }
    if (q == 0) {
        float inv = 1.f / fmaxf((float)(end - beg), 1.f);
        float4* outp = reinterpret_cast<float4*>(g_pa + (size_t)d * DEMB + sub * 8);
        outp[0] = make_float4(acc[0] * inv, acc[1] * inv, acc[2] * inv, acc[3] * inv);
        outp[1] = make_float4(acc[4] * inv, acc[5] * inv, acc[6] * inv, acc[7] * inv);
    }
}

// ---------------- half-MLP: OutT[k][r] = sum_d (pa[node_r][d] + b2[d]) * Whalf[d][k] (+bm1[k]) ------
__global__ __launch_bounds__(128) void half_mlp_kernel(
    const int* __restrict__ list, int nrows,
    const float* __restrict__ Whalf, const float* __restrict__ b2,
    const float* __restrict__ bm1, float* __restrict__ OutT, int ldo) {
    __shared__ __align__(8) float Wst[128 * 66];   // transposed [t][d], pad 66 (even) for ull loads
    __shared__ __align__(8) float es[DEMB];
    int tid = threadIdx.x;  // 128 (= t)

#pragma unroll 4
    for (int d = 0; d < DEMB; d++) Wst[tid * 66 + d] = Whalf[d * DIM + tid];
    float base = bm1 ? bm1[tid] : 0.f;

    for (int r = blockIdx.x; r < nrows; r += gridDim.x) {
        __syncthreads();
        if (tid < DEMB) {
            int node = NUMP + list[r];
            es[tid] = g_pa[(size_t)node * DEMB + tid] + b2[tid];
        }
        __syncthreads();
        ull acc = 0ull;
#pragma unroll 8
        for (int d = 0; d < DEMB; d += 2) {
            ull ep = *reinterpret_cast<const ull*>(es + d);
            ull wp = *reinterpret_cast<const ull*>(Wst + tid * 66 + d);
            acc = ffma2(ep, wp, acc);
        }
        float2 a2 = unpack2(acc);
        OutT[(size_t)tid * ldo + r] = base + a2.x + a2.y;
    }
}

// ---------------- pair kernel: out[t*NG+g] = softmax( relu(A[t]+B[g]) @ Wm2 + bm2 ) ----------------
__global__ __launch_bounds__(256) void pair_kernel(
    const float* __restrict__ Wm2, const float* __restrict__ bm2, float* __restrict__ out) {
    extern __shared__ float sm[];
    float* As = sm;                       // [k][t] 128*128
    float* Bs = sm + DIM * NT;            // [k][gl] 128*32
    float2* w2 = reinterpret_cast<float2*>(sm + DIM * NT + DIM * 32);
    int tid = threadIdx.x;  // 256

    for (int i = tid; i < DIM * NT / 4; i += 256)
        reinterpret_cast<float4*>(As)[i] = reinterpret_cast<const float4*>(g_At)[i];
    int g0 = blockIdx.x * 32;
    for (int i = tid; i < DIM * 32; i += 256) {
        int k = i >> 5, gl = i & 31;
        Bs[i] = g_Bt[(size_t)k * NG + g0 + gl];
    }
    if (tid < DIM) w2[tid] = reinterpret_cast<const float2*>(Wm2)[tid];
    __syncthreads();

    float bo0 = bm2[0], bo1 = bm2[1];
    int lane = tid & 31, warp = tid >> 5;
    ull accp[16];
#pragma unroll
    for (int i = 0; i < 16; i++) accp[i] = 0ull;

#pragma unroll 4
    for (int k = 0; k < DIM; k++) {
        float bv = Bs[k * 32 + lane];
        ull wp = *reinterpret_cast<const ull*>(&w2[k]);
#pragma unroll
        for (int i = 0; i < 16; i++) {
            float a = As[k * DIM + warp + 8 * i];
            float v = fmaxf(a + bv, 0.f);
            accp[i] = ffma2(bcast2(v), wp, accp[i]);
        }
    }

#pragma unroll
    for (int i = 0; i < 16; i++) {
        int t = warp + 8 * i;
        float2 a2 = unpack2(accp[i]);
        float o0 = a2.x + bo0, o1 = a2.y + bo1;
        float m  = fmaxf(o0, o1);
        float e0 = __expf(o0 - m), e1 = __expf(o1 - m);
        float inv = 1.f / (e0 + e1);
        reinterpret_cast<float2*>(out)[(size_t)t * NG + g0 + lane] = make_float2(e0 * inv, e1 * inv);
    }
}

// ---------------- launch ----------------
extern "C" void kernel_launch(void* const* d_in, const int* in_sizes, int n_in,
                              void* d_out, int out_size) {
    const float* x   = (const float*)d_in[0];
    const float* W1  = (const float*)d_in[1];
    const float* b1  = (const float*)d_in[2];
    const float* W2  = (const float*)d_in[3];
    const float* b2  = (const float*)d_in[4];
    const float* Wm1 = (const float*)d_in[5];
    const float* bm1 = (const float*)d_in[6];
    const float* Wm2 = (const float*)d_in[7];
    const float* bm2 = (const float*)d_in[8];
    const int* edges = (const int*)d_in[9];
    const int* tf    = (const int*)d_in[11];
    const int* gene  = (const int*)d_in[12];
    int ne = in_sizes[9] / 2;
    const int* src = edges;
    const int* dst = edges + ne;
    float* out = (float*)d_out;

    const int gemm_smem = (128 + 64 + 64 + 64) * PITCH * 2 + 128 * 4;  // ~87.5 KB
    cudaFuncSetAttribute(hmma_gemm_kernel, cudaFuncAttributeMaxDynamicSharedMemorySize, gemm_smem);
    cudaFuncSetAttribute(pair_kernel, cudaFuncAttributeMaxDynamicSharedMemorySize,
                         (DIM * NT + DIM * 32) * 4 + DIM * 8);

    void *p_At, *p_Bt;
    cudaGetSymbolAddress(&p_At, g_At);
    cudaGetSymbolAddress(&p_Bt, g_Bt);

    const int nb_scan = (NNODES + 1 + 1023) / 1024;  // 79
    int hb = ((ne >> 2) + 255) / 256;
    int fb = (NG + 255) / 256;
    int tb = (DIM * DIM + DIM * DEMB + 255) / 256;   // 96
    int combo_blocks = hb + 5000 + fb + tb;

    zero_kernel<<<(NNODES + 1 + 255) / 256, 256>>>();
    combo_kernel<<<combo_blocks, 256>>>(x, dst, ne, hb, tf, gene, W1, W2);
    scan1_kernel<<<nb_scan, 1024>>>();
    scan2_kernel<<<1, 32>>>(nb_scan);
    scan3_kernel<<<nb_scan, 1024>>>();
    scatter_kernel<<<((ne >> 2) + 255) / 256, 256>>>(src, dst, ne);
    agg1_csr_kernel<<<NNODES / 8, 256>>>();
    hmma_gemm_kernel<<<NNODES / 64, 512, gemm_smem>>>(b1);
    agg2_csr_kernel<<<(NT + NG + 7) / 8, 256>>>();
    half_mlp_kernel<<<NT, 128>>>(tf, NT, Wm1, b2, nullptr, (float*)p_At, NT);
    half_mlp_kernel<<<1000, 128>>>(gene, NG, Wm1 + 64 * DIM, b2, bm1, (float*)p_Bt, NG);
    pair_kernel<<<NG / 32, 256, (DIM * NT + DIM * 32) * 4 + DIM * 8>>>(Wm2, bm2, out);
}

// round 9
// speedup vs baseline: 1.7506x; 1.0554x over previous
#include <cuda_runtime.h>
#include <cuda_fp16.h>
#include <math.h>

#define NNODES 80000
#define DIM    128
#define DEMB   64
#define NT     128
#define NG     8000
#define NUMP   40000
#define NEMAX  2560000
#define PITCH  136   // padded fp16 smem row pitch (bank-conflict-free fragment loads)

typedef unsigned long long ull;

__device__ __forceinline__ ull ffma2(ull a, ull b, ull c) {
    ull d;
    asm("fma.rn.f32x2 %0, %1, %2, %3;" : "=l"(d) : "l"(a), "l"(b), "l"(c));
    return d;
}
__device__ __forceinline__ ull bcast2(float a) {
    ull d;
    asm("mov.b64 %0, {%1, %1};" : "=l"(d) : "f"(a));
    return d;
}
__device__ __forceinline__ float2 unpack2(ull v) {
    float2 f;
    asm("mov.b64 {%0, %1}, %2;" : "=f"(f.x), "=f"(f.y) : "l"(v));
    return f;
}
__device__ __forceinline__ void mma16816(float* d, const unsigned* a, const unsigned* b) {
    asm volatile(
        "mma.sync.aligned.m16n8k16.row.col.f32.f16.f16.f32 "
        "{%0,%1,%2,%3}, {%4,%5,%6,%7}, {%8,%9}, {%0,%1,%2,%3};"
        : "+f"(d[0]), "+f"(d[1]), "+f"(d[2]), "+f"(d[3])
        : "r"(a[0]), "r"(a[1]), "r"(a[2]), "r"(a[3]), "r"(b[0]), "r"(b[1]));
}

// ---------------- scratch (static device arrays; no allocation) ----------------
__device__ int g_rowptr[NNODES + 1];
__device__ int g_flag[NNODES];
__device__ int g_list[NT + NG];
__device__ int g_nlist;
__device__ int g_bsum[128];
__device__ unsigned short g_rank[NEMAX];                       // per-edge rank within dst (u16)
__device__ int g_esrc[NEMAX];                                  // CSR: src per edge, grouped by dst
__device__ __align__(16) __half g_xh [(size_t)NNODES * DIM];   // fp16 copy of x (agg1 gather src)
__device__ __align__(16) __half g_xah[(size_t)NNODES * DIM];   // agg1 output means, fp16
__device__ __align__(16) __half g_w1t[DIM * DIM];              // W1^T fp16 [n][k]
__device__ __align__(16) __half g_w2t[DEMB * DIM];             // W2^T fp16 [n][k]
__device__ __align__(16) __half g_ph[(size_t)NNODES * DEMB];   // relu(agg1@W1+b1)@W2, fp16
__device__ __align__(16) float g_pa[(size_t)NNODES * DEMB];    // agg2 output (listed rows only)
__device__ __align__(16) float g_A [DIM * NT];                 // A row-major [t][k]
__device__ __align__(16) float g_Bt[(size_t)DIM * NG];         // B transposed [k][g]

// ---------------- zero counters/flags ----------------
__global__ void zero_kernel() {
    int i = blockIdx.x * blockDim.x + threadIdx.x;
    if (i <= NNODES) g_rowptr[i] = 0;
    if (i <  NNODES) g_flag[i] = 0;
    if (i == 0) g_nlist = 0;
}

// ---------------- combo: hist+rank(int4) + x->fp16 + flag/list + W transpose/fp16 ----------------
__global__ void combo_kernel(const float* __restrict__ x,
                             const int* __restrict__ dst, int ne, int hb,
                             const int* __restrict__ tf, const int* __restrict__ gene,
                             const float* __restrict__ W1, const float* __restrict__ W2) {
    int b = blockIdx.x;
    const int fb = (NG + 255) / 256;
    if (b < hb) {                       // histogram + rank, 4 edges/thread
        int i = b * 256 + threadIdx.x;
        int ne4 = ne >> 2;
        if (i < ne4) {
            int4 d4 = reinterpret_cast<const int4*>(dst)[i];
            ushort4 r4;
            r4.x = (unsigned short)atomicAdd(&g_rowptr[d4.x + 1], 1);
            r4.y = (unsigned short)atomicAdd(&g_rowptr[d4.y + 1], 1);
            r4.z = (unsigned short)atomicAdd(&g_rowptr[d4.z + 1], 1);
            r4.w = (unsigned short)atomicAdd(&g_rowptr[d4.w + 1], 1);
            reinterpret_cast<ushort4*>(g_rank)[i] = r4;
        }
        if (b == 0 && threadIdx.x == 0) {
            for (int e = ne4 * 4; e < ne; e++)
                g_rank[e] = (unsigned short)atomicAdd(&g_rowptr[dst[e] + 1], 1);
        }
    } else if (b < hb + 5000) {         // x -> fp16 (one thread per 8 floats)
        int i = (b - hb) * 256 + threadIdx.x;
        if (i < NNODES * DIM / 8) {
            float4 a = reinterpret_cast<const float4*>(x)[2 * i];
            float4 bq = reinterpret_cast<const float4*>(x)[2 * i + 1];
            __half2 h0 = __floats2half2_rn(a.x, a.y);
            __half2 h1 = __floats2half2_rn(a.z, a.w);
            __half2 h2 = __floats2half2_rn(bq.x, bq.y);
            __half2 h3 = __floats2half2_rn(bq.z, bq.w);
            uint4 o;
            o.x = *reinterpret_cast<unsigned*>(&h0);
            o.y = *reinterpret_cast<unsigned*>(&h1);
            o.z = *reinterpret_cast<unsigned*>(&h2);
            o.w = *reinterpret_cast<unsigned*>(&h3);
            reinterpret_cast<uint4*>(g_xh)[i] = o;
        }
    } else if (b < hb + 5000 + fb) {    // flag + compact list
        int i = (b - hb - 5000) * 256 + threadIdx.x;
        if (i < NT) {
            int nd = NUMP + tf[i];
            if (atomicExch(&g_flag[nd], 1) == 0) g_list[atomicAdd(&g_nlist, 1)] = nd;
        }
        if (i < NG) {
            int nd = NUMP + gene[i];
            if (atomicExch(&g_flag[nd], 1) == 0) g_list[atomicAdd(&g_nlist, 1)] = nd;
        }
    } else {                            // W1/W2 transpose -> fp16
        int i = (b - hb - 5000 - fb) * 256 + threadIdx.x;
        if (i < DIM * DIM) {
            int k = i >> 7, n = i & 127;
            g_w1t[n * DIM + k] = __float2half(W1[i]);
        } else if (i < DIM * DIM + DIM * DEMB) {
            int j = i - DIM * DIM;
            int k = j >> 6, n = j & 63;
            g_w2t[n * DIM + k] = __float2half(W2[j]);
        }
    }
}

// ---------------- scan over g_rowptr (block-local; bsum = raw block totals) ----------------
__global__ __launch_bounds__(1024) void scan1_kernel() {
    __shared__ int wsum[32];
    int gid = blockIdx.x * 1024 + threadIdx.x;
    int lane = threadIdx.x & 31, wid = threadIdx.x >> 5;
    int s = (gid <= NNODES) ? g_rowptr[gid] : 0;
#pragma unroll
    for (int o = 1; o < 32; o <<= 1) { int t = __shfl_up_sync(0xffffffffu, s, o); if (lane >= o) s += t; }
    if (lane == 31) wsum[wid] = s;
    __syncthreads();
    if (wid == 0) {
        int w = wsum[lane];
#pragma unroll
        for (int o = 1; o < 32; o <<= 1) { int t = __shfl_up_sync(0xffffffffu, w, o); if (lane >= o) w += t; }
        wsum[lane] = w;
    }
    __syncthreads();
    if (wid > 0) s += wsum[wid - 1];
    if (gid <= NNODES) g_rowptr[gid] = s;
    if (threadIdx.x == 1023) g_bsum[blockIdx.x] = s;   // raw block total (inclusive last)
}

// scan3: add prefix of block totals; prefix computed in-block (79 elems, 4 warps)
__global__ __launch_bounds__(1024) void scan3_kernel() {
    __shared__ int s_pre[4];
    int tid = threadIdx.x;
    if (tid < 128) {
        int v = (tid < blockIdx.x) ? g_bsum[tid] : 0;
#pragma unroll
        for (int o = 16; o > 0; o >>= 1) v += __shfl_down_sync(0xffffffffu, v, o);
        if ((tid & 31) == 0) s_pre[tid >> 5] = v;
    }
    __syncthreads();
    int pre = s_pre[0] + s_pre[1] + s_pre[2] + s_pre[3];
    int gid = blockIdx.x * 1024 + tid;
    if (gid <= NNODES) g_rowptr[gid] += pre;
}

// ---------------- scatter (atomic-free): esrc[rowptr[d] + rank[e]] = src[e] ----------------
__global__ void scatter_kernel(const int* __restrict__ src, const int* __restrict__ dst, int ne) {
    int i = blockIdx.x * blockDim.x + threadIdx.x;
    int ne4 = ne >> 2;
    if (i < ne4) {
        int4 s4 = reinterpret_cast<const int4*>(src)[i];
        int4 d4 = reinterpret_cast<const int4*>(dst)[i];
        ushort4 r4 = reinterpret_cast<const ushort4*>(g_rank)[i];
        g_esrc[g_rowptr[d4.x] + r4.x] = s4.x;
        g_esrc[g_rowptr[d4.y] + r4.y] = s4.y;
        g_esrc[g_rowptr[d4.z] + r4.z] = s4.z;
        g_esrc[g_rowptr[d4.w] + r4.w] = s4.w;
    }
    if (i == 0) {
        for (int e = ne4 * 4; e < ne; e++)
            g_esrc[g_rowptr[dst[e]] + g_rank[e]] = src[e];
    }
}

// ---------------- agg1: warp per dst, half-warps gather 2 edges (fp16 rows) -> fp16 means -----
__global__ __launch_bounds__(256) void agg1_csr_kernel() {
    int d = blockIdx.x * 8 + (threadIdx.x >> 5);
    if (d >= NNODES) return;
    int lane = threadIdx.x & 31;
    int half = lane >> 4;       // which edge of the pair
    int sub  = lane & 15;       // 16B chunk within 256B row
    int beg = g_rowptr[d], end = g_rowptr[d + 1];
    float acc[8];
#pragma unroll
    for (int k = 0; k < 8; k++) acc[k] = 0.f;

    int j = beg;
    for (; j + 3 < end; j += 4) {
        int s0 = g_esrc[j + half];
        int s1 = g_esrc[j + 2 + half];
        uint4 va = *reinterpret_cast<const uint4*>(g_xh + (size_t)s0 * DIM + sub * 8);
        uint4 vb = *reinterpret_cast<const uint4*>(g_xh + (size_t)s1 * DIM + sub * 8);
        __half2 p0 = __hadd2(*reinterpret_cast<__half2*>(&va.x), *reinterpret_cast<__half2*>(&vb.x));
        __half2 p1 = __hadd2(*reinterpret_cast<__half2*>(&va.y), *reinterpret_cast<__half2*>(&vb.y));
        __half2 p2 = __hadd2(*reinterpret_cast<__half2*>(&va.z), *reinterpret_cast<__half2*>(&vb.z));
        __half2 p3 = __hadd2(*reinterpret_cast<__half2*>(&va.w), *reinterpret_cast<__half2*>(&vb.w));
        float2 f;
        f = __half22float2(p0); acc[0] += f.x; acc[1] += f.y;
        f = __half22float2(p1); acc[2] += f.x; acc[3] += f.y;
        f = __half22float2(p2); acc[4] += f.x; acc[5] += f.y;
        f = __half22float2(p3); acc[6] += f.x; acc[7] += f.y;
    }
    for (; j < end; j += 2) {
        int jj = j + half;
        if (jj < end) {
            int s = g_esrc[jj];
            uint4 v = *reinterpret_cast<const uint4*>(g_xh + (size_t)s * DIM + sub * 8);
            float2 f;
            f = __half22float2(*reinterpret_cast<__half2*>(&v.x)); acc[0] += f.x; acc[1] += f.y;
            f = __half22float2(*reinterpret_cast<__half2*>(&v.y)); acc[2] += f.x; acc[3] += f.y;
            f = __half22float2(*reinterpret_cast<__half2*>(&v.z)); acc[4] += f.x; acc[5] += f.y;
            f = __half22float2(*reinterpret_cast<__half2*>(&v.w)); acc[6] += f.x; acc[7] += f.y;
        }
    }
#pragma unroll
    for (int k = 0; k < 8; k++) acc[k] += __shfl_xor_sync(0xffffffffu, acc[k], 16);
    if (half == 0) {
        float inv = 1.f / fmaxf((float)(end - beg), 1.f);
        __half2 h0 = __floats2half2_rn(acc[0] * inv, acc[1] * inv);
        __half2 h1 = __floats2half2_rn(acc[2] * inv, acc[3] * inv);
        __half2 h2 = __floats2half2_rn(acc[4] * inv, acc[5] * inv);
        __half2 h3 = __floats2half2_rn(acc[6] * inv, acc[7] * inv);
        uint4 o;
        o.x = *reinterpret_cast<unsigned*>(&h0);
        o.y = *reinterpret_cast<unsigned*>(&h1);
        o.z = *reinterpret_cast<unsigned*>(&h2);
        o.w = *reinterpret_cast<unsigned*>(&h3);
        *reinterpret_cast<uint4*>(g_xah + (size_t)d * DIM + sub * 8) = o;
    }
}

// ---------------- HMMA GEMM: ph = relu(xah @ W1 + b1) @ W2  (64 rows/block, 512 thr) ----------
__global__ __launch_bounds__(512) void hmma_gemm_kernel(const float* __restrict__ b1) {
    extern __shared__ __half hsm[];
    __half* W1s = hsm;                    // 128 x PITCH
    __half* W2s = W1s + 128 * PITCH;      // 64 x PITCH
    __half* Is  = W2s + 64 * PITCH;       // 64 x PITCH
    __half* Hs  = Is  + 64 * PITCH;       // 64 x PITCH
    float*  b1s = reinterpret_cast<float*>(Hs + 64 * PITCH);  // 128 floats
    int tid = threadIdx.x;
    int row0 = blockIdx.x * 64;  // 1250 * 64 = 80000 exact

    for (int i = tid; i < 128 * 16; i += 512) {
        int n = i >> 4, ch = i & 15;
        reinterpret_cast<uint4*>(W1s + n * PITCH)[ch] =
            reinterpret_cast<const uint4*>(g_w1t + n * DIM)[ch];
    }
    for (int i = tid; i < 64 * 16; i += 512) {
        int n = i >> 4, ch = i & 15;
        reinterpret_cast<uint4*>(W2s + n * PITCH)[ch] =
            reinterpret_cast<const uint4*>(g_w2t + n * DIM)[ch];
    }
    for (int i = tid; i < 64 * 16; i += 512) {
        int r = i >> 4, ch = i & 15;
        reinterpret_cast<uint4*>(Is + r * PITCH)[ch] =
            reinterpret_cast<const uint4*>(g_xah + (size_t)(row0 + r) * DIM)[ch];
    }
    if (tid < 128) b1s[tid] = b1[tid];
    __syncthreads();

    int warp = tid >> 5, lane = tid & 31;
    int g = lane >> 2, c = lane & 3;

    // phase 1: H(64x128) = relu(Is @ W1^T-frag + b1) ; warp tile 16x32
    {
        int r0 = (warp & 3) * 16, c0 = (warp >> 2) * 32;
        float d[4][4];
#pragma unroll
        for (int nt = 0; nt < 4; nt++)
#pragma unroll
            for (int q = 0; q < 4; q++) d[nt][q] = 0.f;

#pragma unroll
        for (int k0 = 0; k0 < 128; k0 += 16) {
            unsigned a[4];
            const __half* ip = Is + (r0 + g) * PITCH + k0 + 2 * c;
            a[0] = *reinterpret_cast<const unsigned*>(ip);
            a[1] = *reinterpret_cast<const unsigned*>(ip + 8 * PITCH);
            a[2] = *reinterpret_cast<const unsigned*>(ip + 8);
            a[3] = *reinterpret_cast<const unsigned*>(ip + 8 * PITCH + 8);
#pragma unroll
            for (int nt = 0; nt < 4; nt++) {
                const __half* wp = W1s + (c0 + nt * 8 + g) * PITCH + k0 + 2 * c;
                unsigned bb[2];
                bb[0] = *reinterpret_cast<const unsigned*>(wp);
                bb[1] = *reinterpret_cast<const unsigned*>(wp + 8);
                mma16816(d[nt], a, bb);
            }
        }
#pragma unroll
        for (int nt = 0; nt < 4; nt++) {
            int col = c0 + nt * 8 + 2 * c;
            float bx = b1s[col], by = b1s[col + 1];
            __half2 lo = __floats2half2_rn(fmaxf(d[nt][0] + bx, 0.f), fmaxf(d[nt][1] + by, 0.f));
            __half2 hi = __floats2half2_rn(fmaxf(d[nt][2] + bx, 0.f), fmaxf(d[nt][3] + by, 0.f));
            *reinterpret_cast<__half2*>(Hs + (r0 + g) * PITCH + col) = lo;
            *reinterpret_cast<__half2*>(Hs + (r0 + g + 8) * PITCH + col) = hi;
        }
    }
    __syncthreads();

    // phase 2: P(64x64) = Hs @ W2 ; warp tile 16x16, fp16 output
    {
        int r0 = (warp & 3) * 16, c0 = (warp >> 2) * 16;
        float d[2][4];
#pragma unroll
        for (int nt = 0; nt < 2; nt++)
#pragma unroll
            for (int q = 0; q < 4; q++) d[nt][q] = 0.f;

#pragma unroll
        for (int k0 = 0; k0 < 128; k0 += 16) {
            unsigned a[4];
            const __half* hp = Hs + (r0 + g) * PITCH + k0 + 2 * c;
            a[0] = *reinterpret_cast<const unsigned*>(hp);
            a[1] = *reinterpret_cast<const unsigned*>(hp + 8 * PITCH);
            a[2] = *reinterpret_cast<const unsigned*>(hp + 8);
            a[3] = *reinterpret_cast<const unsigned*>(hp + 8 * PITCH + 8);
#pragma unroll
            for (int nt = 0; nt < 2; nt++) {
                const __half* wp = W2s + (c0 + nt * 8 + g) * PITCH + k0 + 2 * c;
                unsigned bb[2];
                bb[0] = *reinterpret_cast<const unsigned*>(wp);
                bb[1] = *reinterpret_cast<const unsigned*>(wp + 8);
                mma16816(d[nt], a, bb);
            }
        }
#pragma unroll
        for (int nt = 0; nt < 2; nt++) {
            int col = c0 + nt * 8 + 2 * c;
            int row = row0 + r0 + g;
            __half2 lo = __floats2half2_rn(d[nt][0], d[nt][1]);
            __half2 hi = __floats2half2_rn(d[nt][2], d[nt][3]);
            *reinterpret_cast<__half2*>(g_ph + (size_t)row * DEMB + col) = lo;
            *reinterpret_cast<__half2*>(g_ph + (size_t)(row + 8) * DEMB + col) = hi;
        }
    }
}

// ---------------- agg2: warp per listed dst, quarter-warps gather 4 edges (fp16 rows, 128B) -----
__global__ __launch_bounds__(256) void agg2_csr_kernel() {
    int idx = blockIdx.x * 8 + (threadIdx.x >> 5);
    if (idx >= g_nlist) return;
    int d = g_list[idx];
    int lane = threadIdx.x & 31;
    int q   = lane >> 3;        // which edge of the quad
    int sub = lane & 7;         // 16B chunk within 128B fp16 row
    int beg = g_rowptr[d], end = g_rowptr[d + 1];
    float acc[8];
#pragma unroll
    for (int k = 0; k < 8; k++) acc[k] = 0.f;

    int j = beg;
    for (; j + 3 < end; j += 4) {
        int s = g_esrc[j + q];
        uint4 v = *reinterpret_cast<const uint4*>(g_ph + (size_t)s * DEMB + sub * 8);
        float2 f;
        f = __half22float2(*reinterpret_cast<__half2*>(&v.x)); acc[0] += f.x; acc[1] += f.y;
        f = __half22float2(*reinterpret_cast<__half2*>(&v.y)); acc[2] += f.x; acc[3] += f.y;
        f = __half22float2(*reinterpret_cast<__half2*>(&v.z)); acc[4] += f.x; acc[5] += f.y;
        f = __half22float2(*reinterpret_cast<__half2*>(&v.w)); acc[6] += f.x; acc[7] += f.y;
    }
    if (j + q < end) {
        int s = g_esrc[j + q];
        uint4 v = *reinterpret_cast<const uint4*>(g_ph + (size_t)s * DEMB + sub * 8);
        float2 f;
        f = __half22float2(*reinterpret_cast<__half2*>(&v.x)); acc[0] += f.x; acc[1] += f.y;
        f = __half22float2(*reinterpret_cast<__half2*>(&v.y)); acc[2] += f.x; acc[3] += f.y;
        f = __half22float2(*reinterpret_cast<__half2*>(&v.z)); acc[4] += f.x; acc[5] += f.y;
        f = __half22float2(*reinterpret_cast<__half2*>(&v.w)); acc[6] += f.x; acc[7] += f.y;
    }
#pragma unroll
    for (int k = 0; k < 8; k++) {
        acc[k] += __shfl_xor_sync(0xffffffffu, acc[k], 8);
        acc[k] += __shfl_xor_sync(0xffffffffu, acc[k], 16);
    }
    if (q == 0) {
        float inv = 1.f / fmaxf((float)(end - beg), 1.f);
        float4* outp = reinterpret_cast<float4*>(g_pa + (size_t)d * DEMB + sub * 8);
        outp[0] = make_float4(acc[0] * inv, acc[1] * inv, acc[2] * inv, acc[3] * inv);
        outp[1] = make_float4(acc[4] * inv, acc[5] * inv, acc[6] * inv, acc[7] * inv);
    }
}

// ---------------- half-MLP: Out[tid*ks + r*rs] = sum_d (pa[node_r][d] + b2[d]) * Whalf[d][tid] (+bm1) --
__global__ __launch_bounds__(128) void half_mlp_kernel(
    const int* __restrict__ list, int nrows,
    const float* __restrict__ Whalf, const float* __restrict__ b2,
    const float* __restrict__ bm1, float* __restrict__ Out, int ks, int rs) {
    __shared__ __align__(8) float Wst[128 * 66];   // transposed [t][d], pad 66 (even) for ull loads
    __shared__ __align__(8) float es[DEMB];
    int tid = threadIdx.x;  // 128 (= t)

#pragma unroll 4
    for (int d = 0; d < DEMB; d++) Wst[tid * 66 + d] = Whalf[d * DIM + tid];
    float base = bm1 ? bm1[tid] : 0.f;

    for (int r = blockIdx.x; r < nrows; r += gridDim.x) {
        __syncthreads();
        if (tid < DEMB) {
            int node = NUMP + list[r];
            es[tid] = g_pa[(size_t)node * DEMB + tid] + b2[tid];
        }
        __syncthreads();
        ull acc = 0ull;
#pragma unroll 8
        for (int d = 0; d < DEMB; d += 2) {
            ull ep = *reinterpret_cast<const ull*>(es + d);
            ull wp = *reinterpret_cast<const ull*>(Wst + tid * 66 + d);
            acc = ffma2(ep, wp, acc);
        }
        float2 a2 = unpack2(acc);
        Out[(size_t)tid * ks + (size_t)r * rs] = base + a2.x + a2.y;
    }
}

// ---------------- pair kernel: out[t*NG+g] = softmax( relu(A[t]+B[g]) @ Wm2 + bm2 ) ----------------
// A row-major [t][k] (broadcast LDS.128), B k-major [k][gl]
__global__ __launch_bounds__(256) void pair_kernel(
    const float* __restrict__ Wm2, const float* __restrict__ bm2, float* __restrict__ out) {
    extern __shared__ float sm[];
    float* As = sm;                       // [t][k] 128*128
    float* Bs = sm + NT * DIM;            // [k][gl] 128*32
    ull*   w2 = reinterpret_cast<ull*>(sm + NT * DIM + DIM * 32);
    int tid = threadIdx.x;  // 256

    for (int i = tid; i < NT * DIM / 4; i += 256)
        reinterpret_cast<float4*>(As)[i] = reinterpret_cast<const float4*>(g_A)[i];
    int g0 = blockIdx.x * 32;
    for (int i = tid; i < DIM * 32; i += 256) {
        int k = i >> 5, gl = i & 31;
        Bs[i] = g_Bt[(size_t)k * NG + g0 + gl];
    }
    if (tid < DIM) w2[tid] = reinterpret_cast<const ull*>(Wm2)[tid];
    __syncthreads();

    float bo0 = bm2[0], bo1 = bm2[1];
    int lane = tid & 31, warp = tid >> 5;
    ull accp[16];
#pragma unroll
    for (int i = 0; i < 16; i++) accp[i] = 0ull;

#pragma unroll 2
    for (int k0 = 0; k0 < DIM; k0 += 4) {
        float bv0 = Bs[(k0 + 0) * 32 + lane];
        float bv1 = Bs[(k0 + 1) * 32 + lane];
        float bv2 = Bs[(k0 + 2) * 32 + lane];
        float bv3 = Bs[(k0 + 3) * 32 + lane];
        ull wp0 = w2[k0 + 0], wp1 = w2[k0 + 1], wp2 = w2[k0 + 2], wp3 = w2[k0 + 3];
#pragma unroll
        for (int i = 0; i < 16; i++) {
            float4 av = *reinterpret_cast<const float4*>(As + (warp + 8 * i) * DIM + k0);
            float v0 = fmaxf(av.x + bv0, 0.f);
            float v1 = fmaxf(av.y + bv1, 0.f);
            float v2 = fmaxf(av.z + bv2, 0.f);
            float v3 = fmaxf(av.w + bv3, 0.f);
            accp[i] = ffma2(bcast2(v0), wp0, accp[i]);
            accp[i] = ffma2(bcast2(v1), wp1, accp[i]);
            accp[i] = ffma2(bcast2(v2), wp2, accp[i]);
            accp[i] = ffma2(bcast2(v3), wp3, accp[i]);
        }
    }

#pragma unroll
    for (int i = 0; i < 16; i++) {
        int t = warp + 8 * i;
        float2 a2 = unpack2(accp[i]);
        float o0 = a2.x + bo0, o1 = a2.y + bo1;
        float m  = fmaxf(o0, o1);
        float e0 = __expf(o0 - m), e1 = __expf(o1 - m);
        float inv = 1.f / (e0 + e1);
        reinterpret_cast<float2*>(out)[(size_t)t * NG + g0 + lane] = make_float2(e0 * inv, e1 * inv);
    }
}

// ---------------- launch ----------------
extern "C" void kernel_launch(void* const* d_in, const int* in_sizes, int n_in,
                              void* d_out, int out_size) {
    const float* x   = (const float*)d_in[0];
    const float* W1  = (const float*)d_in[1];
    const float* b1  = (const float*)d_in[2];
    const float* W2  = (const float*)d_in[3];
    const float* b2  = (const float*)d_in[4];
    const float* Wm1 = (const float*)d_in[5];
    const float* bm1 = (const float*)d_in[6];
    const float* Wm2 = (const float*)d_in[7];
    const float* bm2 = (const float*)d_in[8];
    const int* edges = (const int*)d_in[9];
    const int* tf    = (const int*)d_in[11];
    const int* gene  = (const int*)d_in[12];
    int ne = in_sizes[9] / 2;
    const int* src = edges;
    const int* dst = edges + ne;
    float* out = (float*)d_out;

    const int gemm_smem = (128 + 64 + 64 + 64) * PITCH * 2 + 128 * 4;  // ~87.5 KB
    const int pair_smem = (NT * DIM + DIM * 32) * 4 + DIM * 8;
    cudaFuncSetAttribute(hmma_gemm_kernel, cudaFuncAttributeMaxDynamicSharedMemorySize, gemm_smem);
    cudaFuncSetAttribute(pair_kernel, cudaFuncAttributeMaxDynamicSharedMemorySize, pair_smem);

    void *p_A, *p_Bt;
    cudaGetSymbolAddress(&p_A,  g_A);
    cudaGetSymbolAddress(&p_Bt, g_Bt);

    const int nb_scan = (NNODES + 1 + 1023) / 1024;  // 79
    int hb = ((ne >> 2) + 255) / 256;
    int fb = (NG + 255) / 256;
    int tb = (DIM * DIM + DIM * DEMB + 255) / 256;   // 96
    int combo_blocks = hb + 5000 + fb + tb;

    zero_kernel<<<(NNODES + 1 + 255) / 256, 256>>>();
    combo_kernel<<<combo_blocks, 256>>>(x, dst, ne, hb, tf, gene, W1, W2);
    scan1_kernel<<<nb_scan, 1024>>>();
    scan3_kernel<<<nb_scan, 1024>>>();
    scatter_kernel<<<((ne >> 2) + 255) / 256, 256>>>(src, dst, ne);
    agg1_csr_kernel<<<NNODES / 8, 256>>>();
    hmma_gemm_kernel<<<NNODES / 64, 512, gemm_smem>>>(b1);
    agg2_csr_kernel<<<(NT + NG + 7) / 8, 256>>>();
    half_mlp_kernel<<<NT, 128>>>(tf, NT, Wm1, b2, nullptr, (float*)p_A, 1, DIM);
    half_mlp_kernel<<<1000, 128>>>(gene, NG, Wm1 + 64 * DIM, b2, bm1, (float*)p_Bt, NG, 1);
    pair_kernel<<<NG / 32, 256, pair_smem>>>(Wm2, bm2, out);
}

// round 10
// speedup vs baseline: 1.7701x; 1.0111x over previous
#include <cuda_runtime.h>
#include <cuda_fp16.h>
#include <math.h>

#define NNODES 80000
#define DIM    128
#define DEMB   64
#define NT     128
#define NG     8000
#define NUMP   40000
#define NEMAX  2560000
#define PITCH  136   // padded fp16 smem row pitch (bank-conflict-free fragment loads)

typedef unsigned long long ull;

__device__ __forceinline__ ull ffma2(ull a, ull b, ull c) {
    ull d;
    asm("fma.rn.f32x2 %0, %1, %2, %3;" : "=l"(d) : "l"(a), "l"(b), "l"(c));
    return d;
}
__device__ __forceinline__ ull bcast2(float a) {
    ull d;
    asm("mov.b64 %0, {%1, %1};" : "=l"(d) : "f"(a));
    return d;
}
__device__ __forceinline__ float2 unpack2(ull v) {
    float2 f;
    asm("mov.b64 {%0, %1}, %2;" : "=f"(f.x), "=f"(f.y) : "l"(v));
    return f;
}
__device__ __forceinline__ void mma16816(float* d, const unsigned* a, const unsigned* b) {
    asm volatile(
        "mma.sync.aligned.m16n8k16.row.col.f32.f16.f16.f32 "
        "{%0,%1,%2,%3}, {%4,%5,%6,%7}, {%8,%9}, {%0,%1,%2,%3};"
        : "+f"(d[0]), "+f"(d[1]), "+f"(d[2]), "+f"(d[3])
        : "r"(a[0]), "r"(a[1]), "r"(a[2]), "r"(a[3]), "r"(b[0]), "r"(b[1]));
}

// ---------------- scratch (static device arrays; no allocation) ----------------
__device__ int g_rowptr[NNODES + 1];
__device__ int g_bsum[128];
__device__ int g_scan_done;
__device__ unsigned short g_rank[NEMAX];                       // per-edge rank within dst (u16)
__device__ int g_esrc[NEMAX];                                  // CSR: src per edge, grouped by dst
__device__ __align__(16) __half g_xh [(size_t)NNODES * DIM];   // fp16 copy of x (agg1 gather src)
__device__ __align__(16) __half g_xah[(size_t)NNODES * DIM];   // agg1 output means, fp16
__device__ __align__(16) __half g_w1t[DIM * DIM];              // W1^T fp16 [n][k]
__device__ __align__(16) __half g_w2t[DEMB * DIM];             // W2^T fp16 [n][k]
__device__ __align__(16) __half g_ph[(size_t)NNODES * DEMB];   // relu(agg1@W1+b1)@W2, fp16
__device__ __align__(16) float g_A [DIM * NT];                 // A row-major [t][k]
__device__ __align__(16) float g_Bt[(size_t)DIM * NG];         // B transposed [k][g]

// ---------------- zero counters ----------------
__global__ void zero_kernel() {
    int i = blockIdx.x * blockDim.x + threadIdx.x;
    if (i <= NNODES) g_rowptr[i] = 0;
    if (i == 0) g_scan_done = 0;
}

// ---------------- combo: hist+rank(int4) + x->fp16 + W transpose/fp16 ----------------
__global__ void combo_kernel(const float* __restrict__ x,
                             const int* __restrict__ dst, int ne, int hb,
                             const float* __restrict__ W1, const float* __restrict__ W2) {
    int b = blockIdx.x;
    if (b < hb) {                       // histogram + rank, 4 edges/thread
        int i = b * 256 + threadIdx.x;
        int ne4 = ne >> 2;
        if (i < ne4) {
            int4 d4 = reinterpret_cast<const int4*>(dst)[i];
            ushort4 r4;
            r4.x = (unsigned short)atomicAdd(&g_rowptr[d4.x + 1], 1);
            r4.y = (unsigned short)atomicAdd(&g_rowptr[d4.y + 1], 1);
            r4.z = (unsigned short)atomicAdd(&g_rowptr[d4.z + 1], 1);
            r4.w = (unsigned short)atomicAdd(&g_rowptr[d4.w + 1], 1);
            reinterpret_cast<ushort4*>(g_rank)[i] = r4;
        }
        if (b == 0 && threadIdx.x == 0) {
            for (int e = ne4 * 4; e < ne; e++)
                g_rank[e] = (unsigned short)atomicAdd(&g_rowptr[dst[e] + 1], 1);
        }
    } else if (b < hb + 5000) {         // x -> fp16 (one thread per 8 floats)
        int i = (b - hb) * 256 + threadIdx.x;
        if (i < NNODES * DIM / 8) {
            float4 a = reinterpret_cast<const float4*>(x)[2 * i];
            float4 bq = reinterpret_cast<const float4*>(x)[2 * i + 1];
            __half2 h0 = __floats2half2_rn(a.x, a.y);
            __half2 h1 = __floats2half2_rn(a.z, a.w);
            __half2 h2 = __floats2half2_rn(bq.x, bq.y);
            __half2 h3 = __floats2half2_rn(bq.z, bq.w);
            uint4 o;
            o.x = *reinterpret_cast<unsigned*>(&h0);
            o.y = *reinterpret_cast<unsigned*>(&h1);
            o.z = *reinterpret_cast<unsigned*>(&h2);
            o.w = *reinterpret_cast<unsigned*>(&h3);
            reinterpret_cast<uint4*>(g_xh)[i] = o;
        }
    } else {                            // W1/W2 transpose -> fp16
        int i = (b - hb - 5000) * 256 + threadIdx.x;
        if (i < DIM * DIM) {
            int k = i >> 7, n = i & 127;
            g_w1t[n * DIM + k] = __float2half(W1[i]);
        } else if (i < DIM * DIM + DIM * DEMB) {
            int j = i - DIM * DIM;
            int k = j >> 6, n = j & 63;
            g_w2t[n * DIM + k] = __float2half(W2[j]);
        }
    }
}

// ---------------- single-kernel scan over g_rowptr (79 co-resident blocks, spin on done) -------
__global__ __launch_bounds__(1024) void scan_kernel() {
    __shared__ int wsum[32];
    __shared__ int s_pre[4];
    int gid = blockIdx.x * 1024 + threadIdx.x;
    int lane = threadIdx.x & 31, wid = threadIdx.x >> 5;
    int s = (gid <= NNODES) ? g_rowptr[gid] : 0;
#pragma unroll
    for (int o = 1; o < 32; o <<= 1) { int t = __shfl_up_sync(0xffffffffu, s, o); if (lane >= o) s += t; }
    if (lane == 31) wsum[wid] = s;
    __syncthreads();
    if (wid == 0) {
        int w = wsum[lane];
#pragma unroll
        for (int o = 1; o < 32; o <<= 1) { int t = __shfl_up_sync(0xffffffffu, w, o); if (lane >= o) w += t; }
        wsum[lane] = w;
    }
    __syncthreads();
    if (wid > 0) s += wsum[wid - 1];

    // publish block total, then wait for all blocks
    if (threadIdx.x == 1023) {
        g_bsum[blockIdx.x] = s;
        __threadfence();
        atomicAdd(&g_scan_done, 1);
    }
    if (threadIdx.x == 0) {
        while (atomicAdd(&g_scan_done, 0) < (int)gridDim.x) {}
    }
    __syncthreads();

    // prefix of preceding block totals, computed in-block
    if (threadIdx.x < 128) {
        int v = (threadIdx.x < blockIdx.x) ? *((volatile int*)&g_bsum[threadIdx.x]) : 0;
#pragma unroll
        for (int o = 16; o > 0; o >>= 1) v += __shfl_down_sync(0xffffffffu, v, o);
        if ((threadIdx.x & 31) == 0) s_pre[threadIdx.x >> 5] = v;
    }
    __syncthreads();
    int pre = s_pre[0] + s_pre[1] + s_pre[2] + s_pre[3];
    if (gid <= NNODES) g_rowptr[gid] = s + pre;
}

// ---------------- scatter (atomic-free): esrc[rowptr[d] + rank[e]] = src[e] ----------------
__global__ void scatter_kernel(const int* __restrict__ src, const int* __restrict__ dst, int ne) {
    int i = blockIdx.x * blockDim.x + threadIdx.x;
    int ne4 = ne >> 2;
    if (i < ne4) {
        int4 s4 = reinterpret_cast<const int4*>(src)[i];
        int4 d4 = reinterpret_cast<const int4*>(dst)[i];
        ushort4 r4 = reinterpret_cast<const ushort4*>(g_rank)[i];
        g_esrc[g_rowptr[d4.x] + r4.x] = s4.x;
        g_esrc[g_rowptr[d4.y] + r4.y] = s4.y;
        g_esrc[g_rowptr[d4.z] + r4.z] = s4.z;
        g_esrc[g_rowptr[d4.w] + r4.w] = s4.w;
    }
    if (i == 0) {
        for (int e = ne4 * 4; e < ne; e++)
            g_esrc[g_rowptr[dst[e]] + g_rank[e]] = src[e];
    }
}

// ---------------- agg1: warp per dst, half-warps gather 2 edges (fp16 rows) -> fp16 means -----
__global__ __launch_bounds__(256) void agg1_csr_kernel() {
    int d = blockIdx.x * 8 + (threadIdx.x >> 5);
    if (d >= NNODES) return;
    int lane = threadIdx.x & 31;
    int half = lane >> 4;       // which edge of the pair
    int sub  = lane & 15;       // 16B chunk within 256B row
    int beg = g_rowptr[d], end = g_rowptr[d + 1];
    float acc[8];
#pragma unroll
    for (int k = 0; k < 8; k++) acc[k] = 0.f;

    int j = beg;
    for (; j + 3 < end; j += 4) {
        int s0 = g_esrc[j + half];
        int s1 = g_esrc[j + 2 + half];
        uint4 va = *reinterpret_cast<const uint4*>(g_xh + (size_t)s0 * DIM + sub * 8);
        uint4 vb = *reinterpret_cast<const uint4*>(g_xh + (size_t)s1 * DIM + sub * 8);
        __half2 p0 = __hadd2(*reinterpret_cast<__half2*>(&va.x), *reinterpret_cast<__half2*>(&vb.x));
        __half2 p1 = __hadd2(*reinterpret_cast<__half2*>(&va.y), *reinterpret_cast<__half2*>(&vb.y));
        __half2 p2 = __hadd2(*reinterpret_cast<__half2*>(&va.z), *reinterpret_cast<__half2*>(&vb.z));
        __half2 p3 = __hadd2(*reinterpret_cast<__half2*>(&va.w), *reinterpret_cast<__half2*>(&vb.w));
        float2 f;
        f = __half22float2(p0); acc[0] += f.x; acc[1] += f.y;
        f = __half22float2(p1); acc[2] += f.x; acc[3] += f.y;
        f = __half22float2(p2); acc[4] += f.x; acc[5] += f.y;
        f = __half22float2(p3); acc[6] += f.x; acc[7] += f.y;
    }
    for (; j < end; j += 2) {
        int jj = j + half;
        if (jj < end) {
            int s = g_esrc[jj];
            uint4 v = *reinterpret_cast<const uint4*>(g_xh + (size_t)s * DIM + sub * 8);
            float2 f;
            f = __half22float2(*reinterpret_cast<__half2*>(&v.x)); acc[0] += f.x; acc[1] += f.y;
            f = __half22float2(*reinterpret_cast<__half2*>(&v.y)); acc[2] += f.x; acc[3] += f.y;
            f = __half22float2(*reinterpret_cast<__half2*>(&v.z)); acc[4] += f.x; acc[5] += f.y;
            f = __half22float2(*reinterpret_cast<__half2*>(&v.w)); acc[6] += f.x; acc[7] += f.y;
        }
    }
#pragma unroll
    for (int k = 0; k < 8; k++) acc[k] += __shfl_xor_sync(0xffffffffu, acc[k], 16);
    if (half == 0) {
        float inv = 1.f / fmaxf((float)(end - beg), 1.f);
        __half2 h0 = __floats2half2_rn(acc[0] * inv, acc[1] * inv);
        __half2 h1 = __floats2half2_rn(acc[2] * inv, acc[3] * inv);
        __half2 h2 = __floats2half2_rn(acc[4] * inv, acc[5] * inv);
        __half2 h3 = __floats2half2_rn(acc[6] * inv, acc[7] * inv);
        uint4 o;
        o.x = *reinterpret_cast<unsigned*>(&h0);
        o.y = *reinterpret_cast<unsigned*>(&h1);
        o.z = *reinterpret_cast<unsigned*>(&h2);
        o.w = *reinterpret_cast<unsigned*>(&h3);
        *reinterpret_cast<uint4*>(g_xah + (size_t)d * DIM + sub * 8) = o;
    }
}

// ---------------- HMMA GEMM: ph = relu(xah @ W1 + b1) @ W2  (64 rows/block, 512 thr) ----------
__global__ __launch_bounds__(512) void hmma_gemm_kernel(const float* __restrict__ b1) {
    extern __shared__ __half hsm[];
    __half* W1s = hsm;                    // 128 x PITCH
    __half* W2s = W1s + 128 * PITCH;      // 64 x PITCH
    __half* Is  = W2s + 64 * PITCH;       // 64 x PITCH
    __half* Hs  = Is  + 64 * PITCH;       // 64 x PITCH
    float*  b1s = reinterpret_cast<float*>(Hs + 64 * PITCH);  // 128 floats
    int tid = threadIdx.x;
    int row0 = blockIdx.x * 64;  // 1250 * 64 = 80000 exact

    for (int i = tid; i < 128 * 16; i += 512) {
        int n = i >> 4, ch = i & 15;
        reinterpret_cast<uint4*>(W1s + n * PITCH)[ch] =
            reinterpret_cast<const uint4*>(g_w1t + n * DIM)[ch];
    }
    for (int i = tid; i < 64 * 16; i += 512) {
        int n = i >> 4, ch = i & 15;
        reinterpret_cast<uint4*>(W2s + n * PITCH)[ch] =
            reinterpret_cast<const uint4*>(g_w2t + n * DIM)[ch];
    }
    for (int i = tid; i < 64 * 16; i += 512) {
        int r = i >> 4, ch = i & 15;
        reinterpret_cast<uint4*>(Is + r * PITCH)[ch] =
            reinterpret_cast<const uint4*>(g_xah + (size_t)(row0 + r) * DIM)[ch];
    }
    if (tid < 128) b1s[tid] = b1[tid];
    __syncthreads();

    int warp = tid >> 5, lane = tid & 31;
    int g = lane >> 2, c = lane & 3;

    // phase 1: H(64x128) = relu(Is @ W1^T-frag + b1) ; warp tile 16x32
    {
        int r0 = (warp & 3) * 16, c0 = (warp >> 2) * 32;
        float d[4][4];
#pragma unroll
        for (int nt = 0; nt < 4; nt++)
#pragma unroll
            for (int q = 0; q < 4; q++) d[nt][q] = 0.f;

#pragma unroll
        for (int k0 = 0; k0 < 128; k0 += 16) {
            unsigned a[4];
            const __half* ip = Is + (r0 + g) * PITCH + k0 + 2 * c;
            a[0] = *reinterpret_cast<const unsigned*>(ip);
            a[1] = *reinterpret_cast<const unsigned*>(ip + 8 * PITCH);
            a[2] = *reinterpret_cast<const unsigned*>(ip + 8);
            a[3] = *reinterpret_cast<const unsigned*>(ip + 8 * PITCH + 8);
#pragma unroll
            for (int nt = 0; nt < 4; nt++) {
                const __half* wp = W1s + (c0 + nt * 8 + g) * PITCH + k0 + 2 * c;
                unsigned bb[2];
                bb[0] = *reinterpret_cast<const unsigned*>(wp);
                bb[1] = *reinterpret_cast<const unsigned*>(wp + 8);
                mma16816(d[nt], a, bb);
            }
        }
#pragma unroll
        for (int nt = 0; nt < 4; nt++) {
            int col = c0 + nt * 8 + 2 * c;
            float bx = b1s[col], by = b1s[col + 1];
            __half2 lo = __floats2half2_rn(fmaxf(d[nt][0] + bx, 0.f), fmaxf(d[nt][1] + by, 0.f));
            __half2 hi = __floats2half2_rn(fmaxf(d[nt][2] + bx, 0.f), fmaxf(d[nt][3] + by, 0.f));
            *reinterpret_cast<__half2*>(Hs + (r0 + g) * PITCH + col) = lo;
            *reinterpret_cast<__half2*>(Hs + (r0 + g + 8) * PITCH + col) = hi;
        }
    }
    __syncthreads();

    // phase 2: P(64x64) = Hs @ W2 ; warp tile 16x16, fp16 output
    {
        int r0 = (warp & 3) * 16, c0 = (warp >> 2) * 16;
        float d[2][4];
#pragma unroll
        for (int nt = 0; nt < 2; nt++)
#pragma unroll
            for (int q = 0; q < 4; q++) d[nt][q] = 0.f;

#pragma unroll
        for (int k0 = 0; k0 < 128; k0 += 16) {
            unsigned a[4];
            const __half* hp = Hs + (r0 + g) * PITCH + k0 + 2 * c;
            a[0] = *reinterpret_cast<const unsigned*>(hp);
            a[1] = *reinterpret_cast<const unsigned*>(hp + 8 * PITCH);
            a[2] = *reinterpret_cast<const unsigned*>(hp + 8);
            a[3] = *reinterpret_cast<const unsigned*>(hp + 8 * PITCH + 8);
#pragma unroll
            for (int nt = 0; nt < 2; nt++) {
                const __half* wp = W2s + (c0 + nt * 8 + g) * PITCH + k0 + 2 * c;
                unsigned bb[2];
                bb[0] = *reinterpret_cast<const unsigned*>(wp);
                bb[1] = *reinterpret_cast<const unsigned*>(wp + 8);
                mma16816(d[nt], a, bb);
            }
        }
#pragma unroll
        for (int nt = 0; nt < 2; nt++) {
            int col = c0 + nt * 8 + 2 * c;
            int row = row0 + r0 + g;
            __half2 lo = __floats2half2_rn(d[nt][0], d[nt][1]);
            __half2 hi = __floats2half2_rn(d[nt][2], d[nt][3]);
            *reinterpret_cast<__half2*>(g_ph + (size_t)row * DEMB + col) = lo;
            *reinterpret_cast<__half2*>(g_ph + (size_t)(row + 8) * DEMB + col) = hi;
        }
    }
}

// ---------------- FUSED post: per row -> agg2 (in-block gather-mean of ph) + half-MLP ----------
// blocks 0..NT-1: tf rows (one each, Whalf = Wm1 top, out = g_A row-major [t][k])
// blocks NT..NT+GB-1: gene rows (strided, Whalf = Wm1 bottom + bm1, out = g_Bt [k][g])
__global__ __launch_bounds__(128) void post_kernel(
    const int* __restrict__ tf, const int* __restrict__ gene,
    const float* __restrict__ Wm1, const float* __restrict__ b2,
    const float* __restrict__ bm1, int gb) {
    __shared__ __align__(8) float Wst[128 * 66];
    __shared__ __align__(8) float es[DEMB];
    __shared__ float part[4][DEMB];
    int tid = threadIdx.x;  // 128
    int b = blockIdx.x;
    bool is_tf = (b < NT);
    const float* Whalf = is_tf ? Wm1 : (Wm1 + 64 * DIM);
    const int* list = is_tf ? tf : gene;

#pragma unroll 4
    for (int d = 0; d < DEMB; d++) Wst[tid * 66 + d] = Whalf[d * DIM + tid];
    float base = is_tf ? 0.f : bm1[tid];

    int lane = tid & 31, warp = tid >> 5;
    int sub = tid & 7;          // 16B chunk within 128B fp16 row
    int eg  = tid >> 3;         // edge group 0..15

    int rbeg = is_tf ? b : (b - NT);
    int rend = is_tf ? (b + 1) : NG;
    int rstp = is_tf ? 1 : gb;

    for (int r = rbeg; r < rend; r += rstp) {
        int node = NUMP + list[r];
        int beg = g_rowptr[node], end = g_rowptr[node + 1];
        float acc[8];
#pragma unroll
        for (int k = 0; k < 8; k++) acc[k] = 0.f;
        for (int j = beg + eg; j < end; j += 16) {
            int s = g_esrc[j];
            uint4 v = *reinterpret_cast<const uint4*>(g_ph + (size_t)s * DEMB + sub * 8);
            float2 f;
            f = __half22float2(*reinterpret_cast<__half2*>(&v.x)); acc[0] += f.x; acc[1] += f.y;
            f = __half22float2(*reinterpret_cast<__half2*>(&v.y)); acc[2] += f.x; acc[3] += f.y;
            f = __half22float2(*reinterpret_cast<__half2*>(&v.z)); acc[4] += f.x; acc[5] += f.y;
            f = __half22float2(*reinterpret_cast<__half2*>(&v.w)); acc[6] += f.x; acc[7] += f.y;
        }
        // reduce 4 edge-groups within warp (lanes differ in bits 3,4)
#pragma unroll
        for (int k = 0; k < 8; k++) {
            acc[k] += __shfl_xor_sync(0xffffffffu, acc[k], 8);
            acc[k] += __shfl_xor_sync(0xffffffffu, acc[k], 16);
        }
        __syncthreads();   // protect es/part reuse across iterations
        if (lane < 8) {
#pragma unroll
            for (int k = 0; k < 8; k++) part[warp][lane * 8 + k] = acc[k];
        }
        __syncthreads();
        if (tid < DEMB) {
            float inv = 1.f / fmaxf((float)(end - beg), 1.f);
            es[tid] = (part[0][tid] + part[1][tid] + part[2][tid] + part[3][tid]) * inv + b2[tid];
        }
        __syncthreads();

        ull a2 = 0ull;
#pragma unroll 8
        for (int d = 0; d < DEMB; d += 2) {
            ull ep = *reinterpret_cast<const ull*>(es + d);
            ull wp = *reinterpret_cast<const ull*>(Wst + tid * 66 + d);
            a2 = ffma2(ep, wp, a2);
        }
        float2 f2 = unpack2(a2);
        float val = base + f2.x + f2.y;
        if (is_tf) g_A[r * DIM + tid] = val;
        else       g_Bt[(size_t)tid * NG + r] = val;
    }
}

// ---------------- pair kernel: out[t*NG+g] = softmax( relu(A[t]+B[g]) @ Wm2 + bm2 ) ----------------
__global__ __launch_bounds__(256) void pair_kernel(
    const float* __restrict__ Wm2, const float* __restrict__ bm2, float* __restrict__ out) {
    extern __shared__ float sm[];
    float* As = sm;                       // [t][k] 128*128
    float* Bs = sm + NT * DIM;            // [k][gl] 128*32
    ull*   w2 = reinterpret_cast<ull*>(sm + NT * DIM + DIM * 32);
    int tid = threadIdx.x;  // 256

    for (int i = tid; i < NT * DIM / 4; i += 256)
        reinterpret_cast<float4*>(As)[i] = reinterpret_cast<const float4*>(g_A)[i];
    int g0 = blockIdx.x * 32;
    for (int i = tid; i < DIM * 32; i += 256) {
        int k = i >> 5, gl = i & 31;
        Bs[i] = g_Bt[(size_t)k * NG + g0 + gl];
    }
    if (tid < DIM) w2[tid] = reinterpret_cast<const ull*>(Wm2)[tid];
    __syncthreads();

    float bo0 = bm2[0], bo1 = bm2[1];
    int lane = tid & 31, warp = tid >> 5;
    ull accp[16];
#pragma unroll
    for (int i = 0; i < 16; i++) accp[i] = 0ull;

#pragma unroll 2
    for (int k0 = 0; k0 < DIM; k0 += 4) {
        float bv0 = Bs[(k0 + 0) * 32 + lane];
        float bv1 = Bs[(k0 + 1) * 32 + lane];
        float bv2 = Bs[(k0 + 2) * 32 + lane];
        float bv3 = Bs[(k0 + 3) * 32 + lane];
        ull wp0 = w2[k0 + 0], wp1 = w2[k0 + 1], wp2 = w2[k0 + 2], wp3 = w2[k0 + 3];
#pragma unroll
        for (int i = 0; i < 16; i++) {
            float4 av = *reinterpret_cast<const float4*>(As + (warp + 8 * i) * DIM + k0);
            float v0 = fmaxf(av.x + bv0, 0.f);
            float v1 = fmaxf(av.y + bv1, 0.f);
            float v2 = fmaxf(av.z + bv2, 0.f);
            float v3 = fmaxf(av.w + bv3, 0.f);
            accp[i] = ffma2(bcast2(v0), wp0, accp[i]);
            accp[i] = ffma2(bcast2(v1), wp1, accp[i]);
            accp[i] = ffma2(bcast2(v2), wp2, accp[i]);
            accp[i] = ffma2(bcast2(v3), wp3, accp[i]);
        }
    }

#pragma unroll
    for (int i = 0; i < 16; i++) {
        int t = warp + 8 * i;
        float2 a2 = unpack2(accp[i]);
        float o0 = a2.x + bo0, o1 = a2.y + bo1;
        float m  = fmaxf(o0, o1);
        float e0 = __expf(o0 - m), e1 = __expf(o1 - m);
        float inv = 1.f / (e0 + e1);
        reinterpret_cast<float2*>(out)[(size_t)t * NG + g0 + lane] = make_float2(e0 * inv, e1 * inv);
    }
}

// ---------------- launch ----------------
extern "C" void kernel_launch(void* const* d_in, const int* in_sizes, int n_in,
                              void* d_out, int out_size) {
    const float* x   = (const float*)d_in[0];
    const float* W1  = (const float*)d_in[1];
    const float* b1  = (const float*)d_in[2];
    const float* W2  = (const float*)d_in[3];
    const float* b2  = (const float*)d_in[4];
    const float* Wm1 = (const float*)d_in[5];
    const float* bm1 = (const float*)d_in[6];
    const float* Wm2 = (const float*)d_in[7];
    const float* bm2 = (const float*)d_in[8];
    const int* edges = (const int*)d_in[9];
    const int* tf    = (const int*)d_in[11];
    const int* gene  = (const int*)d_in[12];
    int ne = in_sizes[9] / 2;
    const int* src = edges;
    const int* dst = edges + ne;
    float* out = (float*)d_out;

    const int gemm_smem = (128 + 64 + 64 + 64) * PITCH * 2 + 128 * 4;  // ~87.5 KB
    const int pair_smem = (NT * DIM + DIM * 32) * 4 + DIM * 8;
    cudaFuncSetAttribute(hmma_gemm_kernel, cudaFuncAttributeMaxDynamicSharedMemorySize, gemm_smem);
    cudaFuncSetAttribute(pair_kernel, cudaFuncAttributeMaxDynamicSharedMemorySize, pair_smem);

    const int nb_scan = (NNODES + 1 + 1023) / 1024;  // 79
    int hb = ((ne >> 2) + 255) / 256;
    int tb = (DIM * DIM + DIM * DEMB + 255) / 256;   // 96
    int combo_blocks = hb + 5000 + tb;
    const int gb = 1000;                              // gene blocks in post

    zero_kernel<<<(NNODES + 1 + 255) / 256, 256>>>();
    combo_kernel<<<combo_blocks, 256>>>(x, dst, ne, hb, W1, W2);
    scan_kernel<<<nb_scan, 1024>>>();
    scatter_kernel<<<((ne >> 2) + 255) / 256, 256>>>(src, dst, ne);
    agg1_csr_kernel<<<NNODES / 8, 256>>>();
    hmma_gemm_kernel<<<NNODES / 64, 512, gemm_smem>>>(b1);
    post_kernel<<<NT + gb, 128>>>(tf, gene, Wm1, b2, bm1, gb);
    pair_kernel<<<NG / 32, 256, pair_smem>>>(Wm2, bm2, out);
}